// round 14
// baseline (speedup 1.0000x reference)
#include <cuda_runtime.h>
#include <cuda_bf16.h>
#include <math.h>
#include <stdint.h>

#define NN 50000
#define NE 800000
#define HC 256
#define NG 64

#define E2M 0.13533528323661270f

// ---------------- device scratch ----------------
__device__ __nv_bfloat16 g_h[(size_t)NN * HC];   // GAT features (bf16)
__device__ float g_ln[(size_t)50176 * 256];
__device__ float g_as[NN * 4];
__device__ float g_ad[NN * 4];
__device__ int   g_cnt[NN];
__device__ int   g_indptr[NN + 1];
__device__ int   g_cursor[NN];
__device__ int   g_ssrc[NE + NN];
__device__ float g_pooled[NG * HC];
__device__ __nv_bfloat16 g_Wh0[512 * 256];    // bf16 W0, [n][k]
__device__ __nv_bfloat16 g_Wh1[1024 * 256];   // bf16 W1, [n][k]
__device__ int   g_bsum[64];
__device__ int   g_boff[64];

__device__ __forceinline__ uint32_t smem_u32(const void* p) {
    uint32_t a;
    asm("{ .reg .u64 t; cvta.to.shared.u64 t, %1; cvt.u32.u64 %0, t; }" : "=r"(a) : "l"(p));
    return a;
}
__device__ __forceinline__ void cp16(void* dst, const void* src) {
    uint32_t d = smem_u32(dst);
    asm volatile("cp.async.cg.shared.global [%0], [%1], 16;" :: "r"(d), "l"(src) : "memory");
}
#define CP_COMMIT() asm volatile("cp.async.commit_group;" ::: "memory")
#define CP_WAIT(n)  asm volatile("cp.async.wait_group %0;" :: "n"(n) : "memory")

__device__ __forceinline__ void ldsm4(unsigned r[4], uint32_t addr) {
    asm volatile("ldmatrix.sync.aligned.m8n8.x4.shared.b16 {%0,%1,%2,%3}, [%4];"
                 : "=r"(r[0]), "=r"(r[1]), "=r"(r[2]), "=r"(r[3]) : "r"(addr));
}
__device__ __forceinline__ void mma_bf16(float c[4], const unsigned a[4], const unsigned b[2]) {
    asm volatile(
        "mma.sync.aligned.m16n8k16.row.col.f32.bf16.bf16.f32 "
        "{%0,%1,%2,%3}, {%4,%5,%6,%7}, {%8,%9}, {%0,%1,%2,%3};\n"
        : "+f"(c[0]), "+f"(c[1]), "+f"(c[2]), "+f"(c[3])
        : "r"(a[0]), "r"(a[1]), "r"(a[2]), "r"(a[3]), "r"(b[0]), "r"(b[1]));
}
__device__ __forceinline__ unsigned pack_bf16x2(float lo, float hi) {
    unsigned u;
    asm("cvt.rn.bf16x2.f32 %0, %1, %2;" : "=r"(u) : "f"(hi), "f"(lo));
    return u;
}
__device__ __forceinline__ float2 bf2_to_f2(unsigned u) {
    __nv_bfloat162 p = *reinterpret_cast<__nv_bfloat162*>(&u);
    return __bfloat1622float2(p);
}

// RBF basis via geometric recurrence
__device__ __forceinline__ void rbf4(float x, float bv[4]) {
    float xp2 = x + 2.f;
    float b0 = __expf(-0.5625f * xp2 * xp2);
    float r  = __expf(fmaf(1.5f, x, 2.f));
    float rg  = r * E2M;
    float rgg = rg * E2M;
    bv[0] = b0;
    bv[1] = b0 * r;
    bv[2] = bv[1] * rg;
    bv[3] = bv[2] * rgg;
}

// ---------------- CSR build ----------------
__global__ void clear_kernel() {
    int i = blockIdx.x * blockDim.x + threadIdx.x;
    if (i < NN) g_cnt[i] = 0;
    if (i < NG * HC) g_pooled[i] = 0.f;
}
__global__ void hist_kernel(const int* __restrict__ ei) {
    int e = blockIdx.x * blockDim.x + threadIdx.x;
    if (e < NE) atomicAdd(&g_cnt[ei[NE + e]], 1);
}
__global__ void scan_part1() {
    __shared__ int wsum[8];
    int t = threadIdx.x;
    int base = blockIdx.x * 1024 + t * 4;
    int v[4];
#pragma unroll
    for (int j = 0; j < 4; j++) {
        int idx = base + j;
        v[j] = (idx < NN) ? (g_cnt[idx] + 1) : 0;
    }
    int s = v[0] + v[1] + v[2] + v[3];
    int lane = t & 31, w = t >> 5;
    int sc = s;
#pragma unroll
    for (int off = 1; off < 32; off <<= 1) {
        int u = __shfl_up_sync(0xffffffffu, sc, off);
        if (lane >= off) sc += u;
    }
    if (lane == 31) wsum[w] = sc;
    __syncthreads();
    if (t < 8) {
        int ws = wsum[t];
#pragma unroll
        for (int off = 1; off < 8; off <<= 1) {
            int u = __shfl_up_sync(0x000000ffu, ws, off);
            if (t >= off) ws += u;
        }
        wsum[t] = ws;
    }
    __syncthreads();
    int excl = sc - s + (w > 0 ? wsum[w - 1] : 0);
#pragma unroll
    for (int j = 0; j < 4; j++) {
        int idx = base + j;
        if (idx < NN) g_indptr[idx] = excl;
        excl += v[j];
    }
    if (t == 255) g_bsum[blockIdx.x] = wsum[7];
}
__global__ void scan_part2(int nb) {
    __shared__ int w0tot;
    int t = threadIdx.x;
    int v = (t < nb) ? g_bsum[t] : 0;
    int lane = t & 31, w = t >> 5;
    int sc = v;
#pragma unroll
    for (int off = 1; off < 32; off <<= 1) {
        int u = __shfl_up_sync(0xffffffffu, sc, off);
        if (lane >= off) sc += u;
    }
    if (t == 31) w0tot = sc;
    __syncthreads();
    int incl = sc + (w == 1 ? w0tot : 0);
    g_boff[t] = incl - v;
    if (t == 63) g_indptr[NN] = incl;
}
__global__ void scan_part3() {
    int i = blockIdx.x * 1024 + threadIdx.x;
    if (i < NN) g_indptr[i] += g_boff[blockIdx.x];
}
__global__ void init_cursor_kernel() {
    int i = blockIdx.x * blockDim.x + threadIdx.x;
    if (i < NN) {
        int p = g_indptr[i];
        g_ssrc[p] = i;
        g_cursor[i] = p + 1;
    }
}
__global__ void scatter_kernel(const int* __restrict__ ei) {
    int e = blockIdx.x * blockDim.x + threadIdx.x;
    if (e < NE) {
        int s = ei[e];
        int d = ei[NE + e];
        int p = atomicAdd(&g_cursor[d], 1);
        g_ssrc[p] = s;
    }
}
__global__ void cvt_w_kernel(const float* __restrict__ W, __nv_bfloat16* __restrict__ out, int n4) {
    int i = blockIdx.x * blockDim.x + threadIdx.x;
    if (i < n4) {
        float4 v = reinterpret_cast<const float4*>(W)[i];
        uint2 o;
        o.x = pack_bf16x2(v.x, v.y);
        o.y = pack_bf16x2(v.z, v.w);
        reinterpret_cast<uint2*>(out)[i] = o;
    }
}

// ---------------- LayerNorm (layer 0 input only) ----------------
__global__ void ln128_kernel(const float* __restrict__ X, const float* __restrict__ g,
                             const float* __restrict__ b, float* __restrict__ out)
{
    int warp = (blockIdx.x * blockDim.x + threadIdx.x) >> 5;
    int lane = threadIdx.x & 31;
    if (warp >= NN) return;
    const float* xr = X + (size_t)warp * 128;
    float4 v = *reinterpret_cast<const float4*>(&xr[lane * 4]);
    float s = v.x + v.y + v.z + v.w;
    float ss = v.x * v.x + v.y * v.y + v.z * v.z + v.w * v.w;
#pragma unroll
    for (int off = 16; off > 0; off >>= 1) {
        s  += __shfl_xor_sync(0xffffffffu, s, off);
        ss += __shfl_xor_sync(0xffffffffu, ss, off);
    }
    float mean = s / 128.f;
    float rstd = rsqrtf(ss / 128.f - mean * mean + 1e-5f);
    int d = lane * 4;
    float4 gg = *reinterpret_cast<const float4*>(&g[d]);
    float4 bb = *reinterpret_cast<const float4*>(&b[d]);
    float4 o;
    o.x = (v.x - mean) * rstd * gg.x + bb.x;
    o.y = (v.y - mean) * rstd * gg.y + bb.y;
    o.z = (v.z - mean) * rstd * gg.z + bb.z;
    o.w = (v.w - mean) * rstd * gg.w + bb.w;
    *reinterpret_cast<float4*>(&out[(size_t)warp * 128 + d]) = o;
}

// ---------------- bf16 GEMM: BM=64 BN=256 BK=64 (R11 config) + mbase ----------------
#define STG_BYTES 40960
#define SM_BYTES_BF (2 * STG_BYTES)

template <int D>
__global__ void __launch_bounds__(256, 2)
kan_bf16(const float* __restrict__ LN, const __nv_bfloat16* __restrict__ Wh,
         const float* __restrict__ attS, const float* __restrict__ attD,
         __nv_bfloat16* __restrict__ out, int mbase)
{
    extern __shared__ char smc[];
    const int K = 4 * D, T = K / 64;
    const int t = threadIdx.x;
    const int wid = t >> 5, lane = t & 31;
    const int wm = wid & 1, wn = wid >> 1;
    const int g4 = lane >> 2, tg = lane & 3;
    const int m0 = mbase + blockIdx.x * 64;
    const int head = wn;

    const int arow = t >> 2;
    const int adq  = t & 3;

    float c[2][8][4];
#pragma unroll
    for (int mt = 0; mt < 2; mt++)
#pragma unroll
        for (int nt = 0; nt < 8; nt++)
#pragma unroll
            for (int i = 0; i < 4; i++) c[mt][nt][i] = 0.f;

#define FILLB(S, KT) do {                                                          \
        char* Ab_ = smc + (S) * STG_BYTES;                                         \
        char* Bb_ = Ab_ + 8192;                                                    \
        _Pragma("unroll")                                                          \
        for (int i = 0; i < 8; i++) {                                              \
            int idx = i * 256 + t;                                                 \
            int row = idx >> 3, ch = idx & 7;                                      \
            const __nv_bfloat16* src = &Wh[(size_t)row * K + (KT) * 64 + ch * 8];  \
            cp16(Bb_ + row * 128 + ((ch ^ (row & 7)) << 4), src);                  \
        }                                                                          \
        CP_COMMIT();                                                               \
        {                                                                          \
            int d0 = (KT) * 16 + adq * 4;                                          \
            int rr = m0 + arow;                                                    \
            const float* lp = &LN[(size_t)(rr < NN ? rr : NN - 1) * D + d0];       \
            float4 lv = *reinterpret_cast<const float4*>(lp);                      \
            float dv[4] = {lv.x, lv.y, lv.z, lv.w};                                \
            unsigned pk[8];                                                        \
            _Pragma("unroll")                                                      \
            for (int j = 0; j < 4; j++) {                                          \
                float bv[4];                                                       \
                rbf4(dv[j], bv);                                                   \
                pk[j * 2]     = pack_bf16x2(bv[0], bv[1]);                         \
                pk[j * 2 + 1] = pack_bf16x2(bv[2], bv[3]);                         \
            }                                                                      \
            _Pragma("unroll")                                                      \
            for (int q = 0; q < 2; q++) {                                          \
                int cc = adq * 2 + q;                                              \
                uint4 u = make_uint4(pk[q * 4], pk[q * 4 + 1],                     \
                                     pk[q * 4 + 2], pk[q * 4 + 3]);                \
                *reinterpret_cast<uint4*>(Ab_ + arow * 128 +                        \
                    ((cc ^ (arow & 7)) << 4)) = u;                                 \
            }                                                                      \
        }                                                                          \
    } while (0)

    FILLB(0, 0);

    for (int kt = 0; kt < T; kt++) {
        const int s = kt & 1;
        if (kt + 1 < T) {
            FILLB(s ^ 1, kt + 1);
            CP_WAIT(1);
        } else {
            CP_WAIT(0);
        }
        __syncthreads();
        const char* Ab = smc + s * STG_BYTES;
        const char* Bb = Ab + 8192;
#pragma unroll
        for (int k16 = 0; k16 < 4; k16++) {
            unsigned a[2][4];
#pragma unroll
            for (int mt = 0; mt < 2; mt++) {
                int mrow = wm * 32 + mt * 16 + ((lane >> 3) & 1) * 8 + (lane & 7);
                int c16 = k16 * 2 + (lane >> 4);
                ldsm4(a[mt], smem_u32(Ab + mrow * 128 + ((c16 ^ (mrow & 7)) << 4)));
            }
#pragma unroll
            for (int ntq = 0; ntq < 4; ntq++) {
                int nrow = wn * 64 + (ntq * 2 + (lane >> 4)) * 8 + (lane & 7);
                int c16 = k16 * 2 + ((lane >> 3) & 1);
                unsigned b[4];
                ldsm4(b, smem_u32(Bb + nrow * 128 + ((c16 ^ (nrow & 7)) << 4)));
                mma_bf16(c[0][ntq * 2],     a[0], b);
                mma_bf16(c[0][ntq * 2 + 1], a[0], b + 2);
                mma_bf16(c[1][ntq * 2],     a[1], b);
                mma_bf16(c[1][ntq * 2 + 1], a[1], b + 2);
            }
        }
        __syncthreads();
    }

    // ---- epilogue: fused alphas (warp = one head) + bf16 store of h ----
    float sa[2][2] = {{0.f,0.f},{0.f,0.f}};
    float sd[2][2] = {{0.f,0.f},{0.f,0.f}};
#pragma unroll
    for (int nt = 0; nt < 8; nt++) {
        int cidx = head * 64 + nt * 8 + tg * 2;
        float2 aS = *reinterpret_cast<const float2*>(&attS[cidx]);
        float2 aD = *reinterpret_cast<const float2*>(&attD[cidx]);
#pragma unroll
        for (int mt = 0; mt < 2; mt++) {
            sa[mt][0] += c[mt][nt][0] * aS.x + c[mt][nt][1] * aS.y;
            sa[mt][1] += c[mt][nt][2] * aS.x + c[mt][nt][3] * aS.y;
            sd[mt][0] += c[mt][nt][0] * aD.x + c[mt][nt][1] * aD.y;
            sd[mt][1] += c[mt][nt][2] * aD.x + c[mt][nt][3] * aD.y;
        }
    }
#pragma unroll
    for (int mt = 0; mt < 2; mt++)
#pragma unroll
        for (int hh = 0; hh < 2; hh++) {
            sa[mt][hh] += __shfl_xor_sync(0xffffffffu, sa[mt][hh], 1);
            sa[mt][hh] += __shfl_xor_sync(0xffffffffu, sa[mt][hh], 2);
            sd[mt][hh] += __shfl_xor_sync(0xffffffffu, sd[mt][hh], 1);
            sd[mt][hh] += __shfl_xor_sync(0xffffffffu, sd[mt][hh], 2);
        }

#pragma unroll
    for (int mt = 0; mt < 2; mt++) {
        int r0 = m0 + wm * 32 + mt * 16 + g4;
#pragma unroll
        for (int nt = 0; nt < 8; nt++) {
            int nc = wn * 64 + nt * 8 + tg * 2;
            if (r0 < NN)
                *reinterpret_cast<unsigned*>(&out[(size_t)r0 * 256 + nc]) =
                    pack_bf16x2(c[mt][nt][0], c[mt][nt][1]);
            if (r0 + 8 < NN)
                *reinterpret_cast<unsigned*>(&out[(size_t)(r0 + 8) * 256 + nc]) =
                    pack_bf16x2(c[mt][nt][2], c[mt][nt][3]);
        }
        if (tg == 0) {
            if (r0 < NN)     { g_as[r0 * 4 + head]       = sa[mt][0]; g_ad[r0 * 4 + head]       = sd[mt][0]; }
            if (r0 + 8 < NN) { g_as[(r0 + 8) * 4 + head] = sa[mt][1]; g_ad[(r0 + 8) * 4 + head] = sd[mt][1]; }
        }
    }
#undef FILLB
}

// ---------------- edge aggregation: SINGLE PASS, MLP-4 (R11), + nbase ----------------
__device__ __forceinline__ float leaky(float x) { return x > 0.f ? x : 0.2f * x; }

template <int MODE>
__global__ void aggregate_kernel(const __nv_bfloat16* __restrict__ h,
                                 const float* __restrict__ bias,
                                 const float* __restrict__ lng,
                                 const float* __restrict__ lnb,
                                 const int* __restrict__ batch,
                                 float* __restrict__ out, int nbase)
{
    __shared__ float sp[256];
    __shared__ int bg_s;
    int wid = threadIdx.x >> 5;
    int lane = threadIdx.x & 31;
    int i = nbase + blockIdx.x * 8 + wid;
    bool active = (i < NN);
    if (!active) i = NN - 1;   // keep warp participating in block-level sync

    int my_g = 0;
    if (MODE == 1) {
        my_g = batch[i];
        if (threadIdx.x == 0) bg_s = my_g;
        sp[threadIdx.x] = 0.f;
        __syncthreads();
    }

    int p0 = g_indptr[i];
    int p1 = active ? g_indptr[i + 1] : p0;
    int head = lane >> 3;
    float adh = g_ad[i * 4 + head];

    float acc[8];
#pragma unroll
    for (int k = 0; k < 8; k++) acc[k] = 0.f;
    float den = 0.f;

#define ACC4(U, W) \
    f = bf2_to_f2(U.x); acc[0] += W * f.x; acc[1] += W * f.y; \
    f = bf2_to_f2(U.y); acc[2] += W * f.x; acc[3] += W * f.y; \
    f = bf2_to_f2(U.z); acc[4] += W * f.x; acc[5] += W * f.y; \
    f = bf2_to_f2(U.w); acc[6] += W * f.x; acc[7] += W * f.y;

    int j = p0;
    for (; j + 3 < p1; j += 4) {
        int s0 = g_ssrc[j], s1 = g_ssrc[j + 1], s2 = g_ssrc[j + 2], s3 = g_ssrc[j + 3];
        uint4 u0 = *reinterpret_cast<const uint4*>(h + (size_t)s0 * 256 + lane * 8);
        uint4 u1 = *reinterpret_cast<const uint4*>(h + (size_t)s1 * 256 + lane * 8);
        uint4 u2 = *reinterpret_cast<const uint4*>(h + (size_t)s2 * 256 + lane * 8);
        uint4 u3 = *reinterpret_cast<const uint4*>(h + (size_t)s3 * 256 + lane * 8);
        float a0 = g_as[s0 * 4 + head], a1 = g_as[s1 * 4 + head];
        float a2 = g_as[s2 * 4 + head], a3 = g_as[s3 * 4 + head];
        float w0 = __expf(leaky(a0 + adh));
        float w1 = __expf(leaky(a1 + adh));
        float w2 = __expf(leaky(a2 + adh));
        float w3 = __expf(leaky(a3 + adh));
        den += (w0 + w1) + (w2 + w3);
        float2 f;
        ACC4(u0, w0) ACC4(u1, w1) ACC4(u2, w2) ACC4(u3, w3)
    }
    for (; j < p1; j++) {
        int s = g_ssrc[j];
        uint4 u = *reinterpret_cast<const uint4*>(h + (size_t)s * 256 + lane * 8);
        float w = __expf(leaky(g_as[s * 4 + head] + adh));
        den += w;
        float2 f;
        ACC4(u, w)
    }
#undef ACC4

    float inv = active ? (1.f / den) : 0.f;
    int cb = lane * 8;
    float r[8];
#pragma unroll
    for (int k = 0; k < 8; k++) {
        float v = acc[k] * inv + bias[cb + k];
        r[k] = v / (1.f + __expf(-v));   // silu
        if (!active) r[k] = 0.f;
    }

    if (MODE == 0) {
        float s = 0.f, ss = 0.f;
#pragma unroll
        for (int k = 0; k < 8; k++) { s += r[k]; ss += r[k] * r[k]; }
#pragma unroll
        for (int off = 16; off > 0; off >>= 1) {
            s  += __shfl_xor_sync(0xffffffffu, s, off);
            ss += __shfl_xor_sync(0xffffffffu, ss, off);
        }
        float mean = s / 256.f;
        float rstd = rsqrtf(ss / 256.f - mean * mean + 1e-5f);
        float4 g0 = *reinterpret_cast<const float4*>(&lng[cb]);
        float4 g1 = *reinterpret_cast<const float4*>(&lng[cb + 4]);
        float4 b0 = *reinterpret_cast<const float4*>(&lnb[cb]);
        float4 b1 = *reinterpret_cast<const float4*>(&lnb[cb + 4]);
        float o[8];
        o[0] = (r[0]-mean)*rstd*g0.x + b0.x; o[1] = (r[1]-mean)*rstd*g0.y + b0.y;
        o[2] = (r[2]-mean)*rstd*g0.z + b0.z; o[3] = (r[3]-mean)*rstd*g0.w + b0.w;
        o[4] = (r[4]-mean)*rstd*g1.x + b1.x; o[5] = (r[5]-mean)*rstd*g1.y + b1.y;
        o[6] = (r[6]-mean)*rstd*g1.z + b1.z; o[7] = (r[7]-mean)*rstd*g1.w + b1.w;
        if (active) {
            float* op = out + (size_t)i * 256 + cb;
            *reinterpret_cast<float4*>(op)     = make_float4(o[0], o[1], o[2], o[3]);
            *reinterpret_cast<float4*>(op + 4) = make_float4(o[4], o[5], o[6], o[7]);
        }
    } else {
        int bg = bg_s;
        if (active) {
            if (my_g == bg) {
#pragma unroll
                for (int k = 0; k < 8; k++) atomicAdd(&sp[cb + k], r[k]);
            } else {
#pragma unroll
                for (int k = 0; k < 8; k++) atomicAdd(&g_pooled[my_g * 256 + cb + k], r[k]);
            }
        }
        __syncthreads();
        atomicAdd(&g_pooled[bg * 256 + threadIdx.x], sp[threadIdx.x]);
    }
}

// ---------------- readout ----------------
__global__ void readout_kernel(const float* __restrict__ lng, const float* __restrict__ lnb,
                               const float* __restrict__ Wr, float* __restrict__ out)
{
    __shared__ float bas[1024];
    __shared__ float red[16];
    __shared__ float logit[16];
    __shared__ float mean_s, rstd_s;
    int gidx = blockIdx.x, t = threadIdx.x;
    int lane = t & 31, w = t >> 5;

    float v = g_pooled[gidx * 256 + t];
    float s = v, ss = v * v;
#pragma unroll
    for (int off = 16; off > 0; off >>= 1) {
        s  += __shfl_xor_sync(0xffffffffu, s, off);
        ss += __shfl_xor_sync(0xffffffffu, ss, off);
    }
    if (lane == 0) { red[w] = s; red[8 + w] = ss; }
    __syncthreads();
    if (t == 0) {
        float S = 0.f, SS = 0.f;
        for (int k = 0; k < 8; k++) { S += red[k]; SS += red[8 + k]; }
        float mean = S / 256.f;
        float var  = SS / 256.f - mean * mean;
        mean_s = mean; rstd_s = rsqrtf(var + 1e-5f);
    }
    __syncthreads();
    float ln = (v - mean_s) * rstd_s * lng[t] + lnb[t];
    {
        float bv[4];
        rbf4(ln, bv);
        bas[t * 4 + 0] = bv[0];
        bas[t * 4 + 1] = bv[1];
        bas[t * 4 + 2] = bv[2];
        bas[t * 4 + 3] = bv[3];
    }
    __syncthreads();

    float p0 = 0.f, p1 = 0.f;
    const float* w0 = Wr + (size_t)(2 * w) * 1024;
    const float* w1 = w0 + 1024;
    for (int k = lane; k < 1024; k += 32) {
        float bv = bas[k];
        p0 += bv * w0[k];
        p1 += bv * w1[k];
    }
#pragma unroll
    for (int off = 16; off > 0; off >>= 1) {
        p0 += __shfl_xor_sync(0xffffffffu, p0, off);
        p1 += __shfl_xor_sync(0xffffffffu, p1, off);
    }
    if (lane == 0) { logit[2 * w] = p0; logit[2 * w + 1] = p1; }
    __syncthreads();

    if (t < 32) {
        float l = (lane < 16) ? logit[lane] : -1e30f;
        float m = l;
#pragma unroll
        for (int off = 16; off > 0; off >>= 1)
            m = fmaxf(m, __shfl_xor_sync(0xffffffffu, m, off));
        float ex = (lane < 16) ? __expf(l - m) : 0.f;
        float sum = ex;
#pragma unroll
        for (int off = 16; off > 0; off >>= 1)
            sum += __shfl_xor_sync(0xffffffffu, sum, off);
        if (lane < 16) out[gidx * 16 + lane] = l - m - logf(sum);
    }
}

// ---------------- launch ----------------
extern "C" void kernel_launch(void* const* d_in, const int* in_sizes, int n_in,
                              void* d_out, int out_size)
{
    const float* x     = (const float*)d_in[0];
    const int*   ei    = (const int*)  d_in[1];
    const int*   batch = (const int*)  d_in[2];
    const float* lng0  = (const float*)d_in[3];
    const float* lnb0  = (const float*)d_in[4];
    const float* W0    = (const float*)d_in[5];
    const float* as0   = (const float*)d_in[6];
    const float* ad0   = (const float*)d_in[7];
    const float* b0    = (const float*)d_in[8];
    const float* lng1  = (const float*)d_in[9];
    const float* lnb1  = (const float*)d_in[10];
    const float* W1    = (const float*)d_in[11];
    const float* as1   = (const float*)d_in[12];
    const float* ad1   = (const float*)d_in[13];
    const float* b1    = (const float*)d_in[14];
    const float* lngr  = (const float*)d_in[15];
    const float* lnbr  = (const float*)d_in[16];
    const float* Wr    = (const float*)d_in[17];
    float* out = (float*)d_out;

    float *ln_p;
    __nv_bfloat16 *h_p, *wh0_p, *wh1_p;
    cudaGetSymbolAddress((void**)&h_p,    g_h);
    cudaGetSymbolAddress((void**)&ln_p,   g_ln);
    cudaGetSymbolAddress((void**)&wh0_p,  g_Wh0);
    cudaGetSymbolAddress((void**)&wh1_p,  g_Wh1);

    static cudaStream_t s2 = nullptr, s3 = nullptr;
    static cudaEvent_t ev_fork = nullptr, ev_side = nullptr, ev_w0 = nullptr;
    static cudaEvent_t ev_a0A = nullptr, ev_a0B = nullptr, ev_k2 = nullptr;
    if (!s2) {
        cudaStreamCreateWithFlags(&s2, cudaStreamNonBlocking);
        cudaStreamCreateWithFlags(&s3, cudaStreamNonBlocking);
        cudaEventCreateWithFlags(&ev_fork, cudaEventDisableTiming);
        cudaEventCreateWithFlags(&ev_side, cudaEventDisableTiming);
        cudaEventCreateWithFlags(&ev_w0, cudaEventDisableTiming);
        cudaEventCreateWithFlags(&ev_a0A, cudaEventDisableTiming);
        cudaEventCreateWithFlags(&ev_a0B, cudaEventDisableTiming);
        cudaEventCreateWithFlags(&ev_k2, cudaEventDisableTiming);
    }

    cudaFuncSetAttribute(kan_bf16<128>, cudaFuncAttributeMaxDynamicSharedMemorySize, SM_BYTES_BF);
    cudaFuncSetAttribute(kan_bf16<256>, cudaFuncAttributeMaxDynamicSharedMemorySize, SM_BYTES_BF);

    const int TPB = 256;
    const int scan_blocks = (NN + 1023) / 1024;
    int warp_blocks = (NN * 32 + TPB - 1) / TPB;   // 6250
    int gemm_blocks = (NN + 63) / 64;              // 782

    // chunk boundary: 25024 = 391*64 = 3128*8
    const int HALF   = 25024;
    const int A0A_B  = HALF / 8;                   // 3128 blocks
    const int A0B_B  = (NN - HALF + 7) / 8;        // 3122 blocks
    const int K2A_B  = HALF / 64;                  // 391
    const int K2B_B  = (NN - HALF + 63) / 64;      // 391 (covers tail with guards)

    // ---- fork side streams ----
    cudaEventRecord(ev_fork, 0);
    cudaStreamWaitEvent(s2, ev_fork, 0);
    cudaStreamWaitEvent(s3, ev_fork, 0);

    // s2: CSR build + W1 convert
    clear_kernel<<<(NN + TPB - 1) / TPB, TPB, 0, s2>>>();
    hist_kernel<<<(NE + TPB - 1) / TPB, TPB, 0, s2>>>(ei);
    scan_part1<<<scan_blocks, 256, 0, s2>>>();
    scan_part2<<<1, 64, 0, s2>>>(scan_blocks);
    scan_part3<<<scan_blocks, 1024, 0, s2>>>();
    init_cursor_kernel<<<(NN + TPB - 1) / TPB, TPB, 0, s2>>>();
    scatter_kernel<<<(NE + TPB - 1) / TPB, TPB, 0, s2>>>(ei);
    cvt_w_kernel<<<(256 * 1024 / 4 + TPB - 1) / TPB, TPB, 0, s2>>>(W1, wh1_p, 256 * 1024 / 4);
    cudaEventRecord(ev_side, s2);

    // s3: W0 convert, overlaps ln128
    cvt_w_kernel<<<(256 * 512 / 4 + TPB - 1) / TPB, TPB, 0, s3>>>(W0, wh0_p, 256 * 512 / 4);
    cudaEventRecord(ev_w0, s3);

    // ---- main: layer-0 GEMM path ----
    ln128_kernel<<<warp_blocks, TPB>>>(x, lng0, lnb0, ln_p);
    cudaStreamWaitEvent(0, ev_w0, 0);
    kan_bf16<128><<<gemm_blocks, TPB, SM_BYTES_BF>>>(ln_p, wh0_p, as0, ad0, h_p, 0);

    // ---- agg0 / kan256 chunk pipeline ----
    cudaStreamWaitEvent(0, ev_side, 0);
    aggregate_kernel<0><<<A0A_B, TPB>>>(h_p, b0, lng1, lnb1, batch, ln_p, 0);
    cudaEventRecord(ev_a0A, 0);
    aggregate_kernel<0><<<A0B_B, TPB>>>(h_p, b0, lng1, lnb1, batch, ln_p, HALF);
    cudaEventRecord(ev_a0B, 0);

    cudaStreamWaitEvent(s3, ev_a0A, 0);
    kan_bf16<256><<<K2A_B, TPB, SM_BYTES_BF, s3>>>(ln_p, wh1_p, as1, ad1, h_p, 0);
    cudaStreamWaitEvent(s3, ev_a0B, 0);
    kan_bf16<256><<<K2B_B, TPB, SM_BYTES_BF, s3>>>(ln_p, wh1_p, as1, ad1, h_p, HALF);
    cudaEventRecord(ev_k2, s3);

    // ---- tail: agg1 (needs full h) + readout ----
    cudaStreamWaitEvent(0, ev_k2, 0);
    aggregate_kernel<1><<<warp_blocks, TPB>>>(h_p, b1, nullptr, nullptr, batch, nullptr, 0);
    readout_kernel<<<NG, 256>>>(lngr, lnbr, Wr, out);
}

// round 15
// speedup vs baseline: 1.0335x; 1.0335x over previous
#include <cuda_runtime.h>
#include <cuda_bf16.h>
#include <math.h>
#include <stdint.h>

#define NN 50000
#define NE 800000
#define HC 256
#define NG 64

#define E2M 0.13533528323661270f

// ---------------- device scratch ----------------
__device__ __nv_bfloat16 g_h[(size_t)NN * HC];   // GAT features (bf16)
__device__ float g_ln[(size_t)50176 * 256];
__device__ float g_as[NN * 4];
__device__ float g_ad[NN * 4];
__device__ int   g_cnt[NN];
__device__ int   g_indptr[NN + 1];
__device__ int   g_cursor[NN];
__device__ int   g_ssrc[NE + NN];
__device__ float g_pooled[NG * HC];
__device__ __nv_bfloat16 g_Wh0[512 * 256];    // bf16 W0, [n][k]
__device__ __nv_bfloat16 g_Wh1[1024 * 256];   // bf16 W1, [n][k]
__device__ int   g_bsum[64];
__device__ int   g_boff[64];

__device__ __forceinline__ uint32_t smem_u32(const void* p) {
    uint32_t a;
    asm("{ .reg .u64 t; cvta.to.shared.u64 t, %1; cvt.u32.u64 %0, t; }" : "=r"(a) : "l"(p));
    return a;
}
__device__ __forceinline__ void cp16(void* dst, const void* src) {
    uint32_t d = smem_u32(dst);
    asm volatile("cp.async.cg.shared.global [%0], [%1], 16;" :: "r"(d), "l"(src) : "memory");
}
#define CP_COMMIT() asm volatile("cp.async.commit_group;" ::: "memory")
#define CP_WAIT(n)  asm volatile("cp.async.wait_group %0;" :: "n"(n) : "memory")

__device__ __forceinline__ void ldsm4(unsigned r[4], uint32_t addr) {
    asm volatile("ldmatrix.sync.aligned.m8n8.x4.shared.b16 {%0,%1,%2,%3}, [%4];"
                 : "=r"(r[0]), "=r"(r[1]), "=r"(r[2]), "=r"(r[3]) : "r"(addr));
}
__device__ __forceinline__ void mma_bf16(float c[4], const unsigned a[4], const unsigned b[2]) {
    asm volatile(
        "mma.sync.aligned.m16n8k16.row.col.f32.bf16.bf16.f32 "
        "{%0,%1,%2,%3}, {%4,%5,%6,%7}, {%8,%9}, {%0,%1,%2,%3};\n"
        : "+f"(c[0]), "+f"(c[1]), "+f"(c[2]), "+f"(c[3])
        : "r"(a[0]), "r"(a[1]), "r"(a[2]), "r"(a[3]), "r"(b[0]), "r"(b[1]));
}
__device__ __forceinline__ unsigned pack_bf16x2(float lo, float hi) {
    unsigned u;
    asm("cvt.rn.bf16x2.f32 %0, %1, %2;" : "=r"(u) : "f"(hi), "f"(lo));
    return u;
}
__device__ __forceinline__ float2 bf2_to_f2(unsigned u) {
    __nv_bfloat162 p = *reinterpret_cast<__nv_bfloat162*>(&u);
    return __bfloat1622float2(p);
}

// RBF basis via geometric recurrence
__device__ __forceinline__ void rbf4(float x, float bv[4]) {
    float xp2 = x + 2.f;
    float b0 = __expf(-0.5625f * xp2 * xp2);
    float r  = __expf(fmaf(1.5f, x, 2.f));
    float rg  = r * E2M;
    float rgg = rg * E2M;
    bv[0] = b0;
    bv[1] = b0 * r;
    bv[2] = bv[1] * rg;
    bv[3] = bv[2] * rgg;
}

// ---------------- CSR build ----------------
__global__ void clear_kernel() {
    int i = blockIdx.x * blockDim.x + threadIdx.x;
    if (i < NN) g_cnt[i] = 0;
    if (i < NG * HC) g_pooled[i] = 0.f;
}
__global__ void hist_kernel(const int* __restrict__ ei) {
    int e = blockIdx.x * blockDim.x + threadIdx.x;
    if (e < NE) atomicAdd(&g_cnt[ei[NE + e]], 1);
}
__global__ void scan_part1() {
    __shared__ int wsum[8];
    int t = threadIdx.x;
    int base = blockIdx.x * 1024 + t * 4;
    int v[4];
#pragma unroll
    for (int j = 0; j < 4; j++) {
        int idx = base + j;
        v[j] = (idx < NN) ? (g_cnt[idx] + 1) : 0;
    }
    int s = v[0] + v[1] + v[2] + v[3];
    int lane = t & 31, w = t >> 5;
    int sc = s;
#pragma unroll
    for (int off = 1; off < 32; off <<= 1) {
        int u = __shfl_up_sync(0xffffffffu, sc, off);
        if (lane >= off) sc += u;
    }
    if (lane == 31) wsum[w] = sc;
    __syncthreads();
    if (t < 8) {
        int ws = wsum[t];
#pragma unroll
        for (int off = 1; off < 8; off <<= 1) {
            int u = __shfl_up_sync(0x000000ffu, ws, off);
            if (t >= off) ws += u;
        }
        wsum[t] = ws;
    }
    __syncthreads();
    int excl = sc - s + (w > 0 ? wsum[w - 1] : 0);
#pragma unroll
    for (int j = 0; j < 4; j++) {
        int idx = base + j;
        if (idx < NN) g_indptr[idx] = excl;
        excl += v[j];
    }
    if (t == 255) g_bsum[blockIdx.x] = wsum[7];
}
__global__ void scan_part2(int nb) {
    __shared__ int w0tot;
    int t = threadIdx.x;
    int v = (t < nb) ? g_bsum[t] : 0;
    int lane = t & 31, w = t >> 5;
    int sc = v;
#pragma unroll
    for (int off = 1; off < 32; off <<= 1) {
        int u = __shfl_up_sync(0xffffffffu, sc, off);
        if (lane >= off) sc += u;
    }
    if (t == 31) w0tot = sc;
    __syncthreads();
    int incl = sc + (w == 1 ? w0tot : 0);
    g_boff[t] = incl - v;
    if (t == 63) g_indptr[NN] = incl;
}
__global__ void scan_part3() {
    int i = blockIdx.x * 1024 + threadIdx.x;
    if (i < NN) g_indptr[i] += g_boff[blockIdx.x];
}
__global__ void init_cursor_kernel() {
    int i = blockIdx.x * blockDim.x + threadIdx.x;
    if (i < NN) {
        int p = g_indptr[i];
        g_ssrc[p] = i;
        g_cursor[i] = p + 1;
    }
}
__global__ void scatter_kernel(const int* __restrict__ ei) {
    int e = blockIdx.x * blockDim.x + threadIdx.x;
    if (e < NE) {
        int s = ei[e];
        int d = ei[NE + e];
        int p = atomicAdd(&g_cursor[d], 1);
        g_ssrc[p] = s;
    }
}
__global__ void cvt_w_kernel(const float* __restrict__ W, __nv_bfloat16* __restrict__ out, int n4) {
    int i = blockIdx.x * blockDim.x + threadIdx.x;
    if (i < n4) {
        float4 v = reinterpret_cast<const float4*>(W)[i];
        uint2 o;
        o.x = pack_bf16x2(v.x, v.y);
        o.y = pack_bf16x2(v.z, v.w);
        reinterpret_cast<uint2*>(out)[i] = o;
    }
}

// ---------------- bf16 GEMM: BM=64 BN=256 BK=64 (R11), optional fused input LN ----------------
#define STG_BYTES 40960
#define SM_BYTES_BF (2 * STG_BYTES)

template <int D, bool FUSE_IN_LN>
__global__ void __launch_bounds__(256, 2)
kan_bf16(const float* __restrict__ X,          // raw input if FUSE_IN_LN, else pre-LN'd
         const float* __restrict__ lng, const float* __restrict__ lnb,
         const __nv_bfloat16* __restrict__ Wh,
         const float* __restrict__ attS, const float* __restrict__ attD,
         __nv_bfloat16* __restrict__ out)
{
    extern __shared__ char smc[];
    __shared__ float meanS[64], rstdS[64];
    const int K = 4 * D, T = K / 64;
    const int t = threadIdx.x;
    const int wid = t >> 5, lane = t & 31;
    const int wm = wid & 1, wn = wid >> 1;
    const int g4 = lane >> 2, tg = lane & 3;
    const int m0 = blockIdx.x * 64;
    const int head = wn;

    const int arow = t >> 2;
    const int adq  = t & 3;

    // ---- fused LN prologue (layer 0 only): per-row mean/rstd over D=128 ----
    if (FUSE_IN_LN) {
        int rr = m0 + arow;
        if (rr >= NN) rr = NN - 1;
        const float* xr = X + (size_t)rr * D + adq * (D / 4);
        float s = 0.f, ss = 0.f;
#pragma unroll
        for (int i = 0; i < D / 16; i++) {
            float4 v = *reinterpret_cast<const float4*>(xr + i * 4);
            s  += v.x + v.y + v.z + v.w;
            ss += v.x * v.x + v.y * v.y + v.z * v.z + v.w * v.w;
        }
        s  += __shfl_xor_sync(0xffffffffu, s, 1);
        s  += __shfl_xor_sync(0xffffffffu, s, 2);
        ss += __shfl_xor_sync(0xffffffffu, ss, 1);
        ss += __shfl_xor_sync(0xffffffffu, ss, 2);
        if (adq == 0) {
            float mean = s / (float)D;
            meanS[arow] = mean;
            rstdS[arow] = rsqrtf(ss / (float)D - mean * mean + 1e-5f);
        }
        __syncthreads();
    }

    float c[2][8][4];
#pragma unroll
    for (int mt = 0; mt < 2; mt++)
#pragma unroll
        for (int nt = 0; nt < 8; nt++)
#pragma unroll
            for (int i = 0; i < 4; i++) c[mt][nt][i] = 0.f;

#define FILLB(S, KT) do {                                                          \
        char* Ab_ = smc + (S) * STG_BYTES;                                         \
        char* Bb_ = Ab_ + 8192;                                                    \
        _Pragma("unroll")                                                          \
        for (int i = 0; i < 8; i++) {                                              \
            int idx = i * 256 + t;                                                 \
            int row = idx >> 3, ch = idx & 7;                                      \
            const __nv_bfloat16* src = &Wh[(size_t)row * K + (KT) * 64 + ch * 8];  \
            cp16(Bb_ + row * 128 + ((ch ^ (row & 7)) << 4), src);                  \
        }                                                                          \
        CP_COMMIT();                                                               \
        {                                                                          \
            int d0 = (KT) * 16 + adq * 4;                                          \
            int rr = m0 + arow;                                                    \
            if (FUSE_IN_LN && rr >= NN) rr = NN - 1;                               \
            const float* lp = &X[(size_t)rr * D + d0];                             \
            float4 lv = *reinterpret_cast<const float4*>(lp);                      \
            float dv[4] = {lv.x, lv.y, lv.z, lv.w};                                \
            if (FUSE_IN_LN) {                                                      \
                float mean = meanS[arow], rstd = rstdS[arow];                      \
                float4 gg = *reinterpret_cast<const float4*>(&lng[d0]);            \
                float4 bb = *reinterpret_cast<const float4*>(&lnb[d0]);            \
                dv[0] = (dv[0] - mean) * rstd * gg.x + bb.x;                       \
                dv[1] = (dv[1] - mean) * rstd * gg.y + bb.y;                       \
                dv[2] = (dv[2] - mean) * rstd * gg.z + bb.z;                       \
                dv[3] = (dv[3] - mean) * rstd * gg.w + bb.w;                       \
            }                                                                      \
            unsigned pk[8];                                                        \
            _Pragma("unroll")                                                      \
            for (int j = 0; j < 4; j++) {                                          \
                float bv[4];                                                       \
                rbf4(dv[j], bv);                                                   \
                pk[j * 2]     = pack_bf16x2(bv[0], bv[1]);                         \
                pk[j * 2 + 1] = pack_bf16x2(bv[2], bv[3]);                         \
            }                                                                      \
            _Pragma("unroll")                                                      \
            for (int q = 0; q < 2; q++) {                                          \
                int cc = adq * 2 + q;                                              \
                uint4 u = make_uint4(pk[q * 4], pk[q * 4 + 1],                     \
                                     pk[q * 4 + 2], pk[q * 4 + 3]);                \
                *reinterpret_cast<uint4*>(Ab_ + arow * 128 +                        \
                    ((cc ^ (arow & 7)) << 4)) = u;                                 \
            }                                                                      \
        }                                                                          \
    } while (0)

    FILLB(0, 0);

    for (int kt = 0; kt < T; kt++) {
        const int s = kt & 1;
        if (kt + 1 < T) {
            FILLB(s ^ 1, kt + 1);
            CP_WAIT(1);
        } else {
            CP_WAIT(0);
        }
        __syncthreads();
        const char* Ab = smc + s * STG_BYTES;
        const char* Bb = Ab + 8192;
#pragma unroll
        for (int k16 = 0; k16 < 4; k16++) {
            unsigned a[2][4];
#pragma unroll
            for (int mt = 0; mt < 2; mt++) {
                int mrow = wm * 32 + mt * 16 + ((lane >> 3) & 1) * 8 + (lane & 7);
                int c16 = k16 * 2 + (lane >> 4);
                ldsm4(a[mt], smem_u32(Ab + mrow * 128 + ((c16 ^ (mrow & 7)) << 4)));
            }
#pragma unroll
            for (int ntq = 0; ntq < 4; ntq++) {
                int nrow = wn * 64 + (ntq * 2 + (lane >> 4)) * 8 + (lane & 7);
                int c16 = k16 * 2 + ((lane >> 3) & 1);
                unsigned b[4];
                ldsm4(b, smem_u32(Bb + nrow * 128 + ((c16 ^ (nrow & 7)) << 4)));
                mma_bf16(c[0][ntq * 2],     a[0], b);
                mma_bf16(c[0][ntq * 2 + 1], a[0], b + 2);
                mma_bf16(c[1][ntq * 2],     a[1], b);
                mma_bf16(c[1][ntq * 2 + 1], a[1], b + 2);
            }
        }
        __syncthreads();
    }

    // ---- epilogue: fused alphas (warp = one head) + bf16 store of h ----
    float sa[2][2] = {{0.f,0.f},{0.f,0.f}};
    float sd[2][2] = {{0.f,0.f},{0.f,0.f}};
#pragma unroll
    for (int nt = 0; nt < 8; nt++) {
        int cidx = head * 64 + nt * 8 + tg * 2;
        float2 aS = *reinterpret_cast<const float2*>(&attS[cidx]);
        float2 aD = *reinterpret_cast<const float2*>(&attD[cidx]);
#pragma unroll
        for (int mt = 0; mt < 2; mt++) {
            sa[mt][0] += c[mt][nt][0] * aS.x + c[mt][nt][1] * aS.y;
            sa[mt][1] += c[mt][nt][2] * aS.x + c[mt][nt][3] * aS.y;
            sd[mt][0] += c[mt][nt][0] * aD.x + c[mt][nt][1] * aD.y;
            sd[mt][1] += c[mt][nt][2] * aD.x + c[mt][nt][3] * aD.y;
        }
    }
#pragma unroll
    for (int mt = 0; mt < 2; mt++)
#pragma unroll
        for (int hh = 0; hh < 2; hh++) {
            sa[mt][hh] += __shfl_xor_sync(0xffffffffu, sa[mt][hh], 1);
            sa[mt][hh] += __shfl_xor_sync(0xffffffffu, sa[mt][hh], 2);
            sd[mt][hh] += __shfl_xor_sync(0xffffffffu, sd[mt][hh], 1);
            sd[mt][hh] += __shfl_xor_sync(0xffffffffu, sd[mt][hh], 2);
        }

#pragma unroll
    for (int mt = 0; mt < 2; mt++) {
        int r0 = m0 + wm * 32 + mt * 16 + g4;
#pragma unroll
        for (int nt = 0; nt < 8; nt++) {
            int nc = wn * 64 + nt * 8 + tg * 2;
            if (r0 < NN)
                *reinterpret_cast<unsigned*>(&out[(size_t)r0 * 256 + nc]) =
                    pack_bf16x2(c[mt][nt][0], c[mt][nt][1]);
            if (r0 + 8 < NN)
                *reinterpret_cast<unsigned*>(&out[(size_t)(r0 + 8) * 256 + nc]) =
                    pack_bf16x2(c[mt][nt][2], c[mt][nt][3]);
        }
        if (tg == 0) {
            if (r0 < NN)     { g_as[r0 * 4 + head]       = sa[mt][0]; g_ad[r0 * 4 + head]       = sd[mt][0]; }
            if (r0 + 8 < NN) { g_as[(r0 + 8) * 4 + head] = sa[mt][1]; g_ad[(r0 + 8) * 4 + head] = sd[mt][1]; }
        }
    }
#undef FILLB
}

// ---------------- edge aggregation: SINGLE PASS, MLP-4 (R11) ----------------
__device__ __forceinline__ float leaky(float x) { return x > 0.f ? x : 0.2f * x; }

template <int MODE>
__global__ void aggregate_kernel(const __nv_bfloat16* __restrict__ h,
                                 const float* __restrict__ bias,
                                 const float* __restrict__ lng,
                                 const float* __restrict__ lnb,
                                 const int* __restrict__ batch,
                                 float* __restrict__ out)
{
    __shared__ float sp[256];
    __shared__ int bg_s;
    int wid = threadIdx.x >> 5;
    int lane = threadIdx.x & 31;
    int i = blockIdx.x * 8 + wid;   // grid covers exactly NN warps

    int my_g = 0;
    if (MODE == 1) {
        my_g = batch[i];
        if (threadIdx.x == 0) bg_s = my_g;
        sp[threadIdx.x] = 0.f;
        __syncthreads();
    }

    int p0 = g_indptr[i];
    int p1 = g_indptr[i + 1];
    int head = lane >> 3;
    float adh = g_ad[i * 4 + head];

    float acc[8];
#pragma unroll
    for (int k = 0; k < 8; k++) acc[k] = 0.f;
    float den = 0.f;

#define ACC4(U, W) \
    f = bf2_to_f2(U.x); acc[0] += W * f.x; acc[1] += W * f.y; \
    f = bf2_to_f2(U.y); acc[2] += W * f.x; acc[3] += W * f.y; \
    f = bf2_to_f2(U.z); acc[4] += W * f.x; acc[5] += W * f.y; \
    f = bf2_to_f2(U.w); acc[6] += W * f.x; acc[7] += W * f.y;

    int j = p0;
    for (; j + 3 < p1; j += 4) {
        int s0 = g_ssrc[j], s1 = g_ssrc[j + 1], s2 = g_ssrc[j + 2], s3 = g_ssrc[j + 3];
        uint4 u0 = *reinterpret_cast<const uint4*>(h + (size_t)s0 * 256 + lane * 8);
        uint4 u1 = *reinterpret_cast<const uint4*>(h + (size_t)s1 * 256 + lane * 8);
        uint4 u2 = *reinterpret_cast<const uint4*>(h + (size_t)s2 * 256 + lane * 8);
        uint4 u3 = *reinterpret_cast<const uint4*>(h + (size_t)s3 * 256 + lane * 8);
        float a0 = g_as[s0 * 4 + head], a1 = g_as[s1 * 4 + head];
        float a2 = g_as[s2 * 4 + head], a3 = g_as[s3 * 4 + head];
        float w0 = __expf(leaky(a0 + adh));
        float w1 = __expf(leaky(a1 + adh));
        float w2 = __expf(leaky(a2 + adh));
        float w3 = __expf(leaky(a3 + adh));
        den += (w0 + w1) + (w2 + w3);
        float2 f;
        ACC4(u0, w0) ACC4(u1, w1) ACC4(u2, w2) ACC4(u3, w3)
    }
    for (; j < p1; j++) {
        int s = g_ssrc[j];
        uint4 u = *reinterpret_cast<const uint4*>(h + (size_t)s * 256 + lane * 8);
        float w = __expf(leaky(g_as[s * 4 + head] + adh));
        den += w;
        float2 f;
        ACC4(u, w)
    }
#undef ACC4

    float inv = 1.f / den;
    int cb = lane * 8;
    float r[8];
#pragma unroll
    for (int k = 0; k < 8; k++) {
        float v = acc[k] * inv + bias[cb + k];
        r[k] = v / (1.f + __expf(-v));   // silu
    }

    if (MODE == 0) {
        float s = 0.f, ss = 0.f;
#pragma unroll
        for (int k = 0; k < 8; k++) { s += r[k]; ss += r[k] * r[k]; }
#pragma unroll
        for (int off = 16; off > 0; off >>= 1) {
            s  += __shfl_xor_sync(0xffffffffu, s, off);
            ss += __shfl_xor_sync(0xffffffffu, ss, off);
        }
        float mean = s / 256.f;
        float rstd = rsqrtf(ss / 256.f - mean * mean + 1e-5f);
        float4 g0 = *reinterpret_cast<const float4*>(&lng[cb]);
        float4 g1 = *reinterpret_cast<const float4*>(&lng[cb + 4]);
        float4 b0 = *reinterpret_cast<const float4*>(&lnb[cb]);
        float4 b1 = *reinterpret_cast<const float4*>(&lnb[cb + 4]);
        float o[8];
        o[0] = (r[0]-mean)*rstd*g0.x + b0.x; o[1] = (r[1]-mean)*rstd*g0.y + b0.y;
        o[2] = (r[2]-mean)*rstd*g0.z + b0.z; o[3] = (r[3]-mean)*rstd*g0.w + b0.w;
        o[4] = (r[4]-mean)*rstd*g1.x + b1.x; o[5] = (r[5]-mean)*rstd*g1.y + b1.y;
        o[6] = (r[6]-mean)*rstd*g1.z + b1.z; o[7] = (r[7]-mean)*rstd*g1.w + b1.w;
        float* op = out + (size_t)i * 256 + cb;
        *reinterpret_cast<float4*>(op)     = make_float4(o[0], o[1], o[2], o[3]);
        *reinterpret_cast<float4*>(op + 4) = make_float4(o[4], o[5], o[6], o[7]);
    } else {
        int bg = bg_s;
        if (my_g == bg) {
#pragma unroll
            for (int k = 0; k < 8; k++) atomicAdd(&sp[cb + k], r[k]);
        } else {
#pragma unroll
            for (int k = 0; k < 8; k++) atomicAdd(&g_pooled[my_g * 256 + cb + k], r[k]);
        }
        __syncthreads();
        atomicAdd(&g_pooled[bg * 256 + threadIdx.x], sp[threadIdx.x]);
    }
}

// ---------------- readout ----------------
__global__ void readout_kernel(const float* __restrict__ lng, const float* __restrict__ lnb,
                               const float* __restrict__ Wr, float* __restrict__ out)
{
    __shared__ float bas[1024];
    __shared__ float red[16];
    __shared__ float logit[16];
    __shared__ float mean_s, rstd_s;
    int gidx = blockIdx.x, t = threadIdx.x;
    int lane = t & 31, w = t >> 5;

    float v = g_pooled[gidx * 256 + t];
    float s = v, ss = v * v;
#pragma unroll
    for (int off = 16; off > 0; off >>= 1) {
        s  += __shfl_xor_sync(0xffffffffu, s, off);
        ss += __shfl_xor_sync(0xffffffffu, ss, off);
    }
    if (lane == 0) { red[w] = s; red[8 + w] = ss; }
    __syncthreads();
    if (t == 0) {
        float S = 0.f, SS = 0.f;
        for (int k = 0; k < 8; k++) { S += red[k]; SS += red[8 + k]; }
        float mean = S / 256.f;
        float var  = SS / 256.f - mean * mean;
        mean_s = mean; rstd_s = rsqrtf(var + 1e-5f);
    }
    __syncthreads();
    float ln = (v - mean_s) * rstd_s * lng[t] + lnb[t];
    {
        float bv[4];
        rbf4(ln, bv);
        bas[t * 4 + 0] = bv[0];
        bas[t * 4 + 1] = bv[1];
        bas[t * 4 + 2] = bv[2];
        bas[t * 4 + 3] = bv[3];
    }
    __syncthreads();

    float p0 = 0.f, p1 = 0.f;
    const float* w0 = Wr + (size_t)(2 * w) * 1024;
    const float* w1 = w0 + 1024;
    for (int k = lane; k < 1024; k += 32) {
        float bv = bas[k];
        p0 += bv * w0[k];
        p1 += bv * w1[k];
    }
#pragma unroll
    for (int off = 16; off > 0; off >>= 1) {
        p0 += __shfl_xor_sync(0xffffffffu, p0, off);
        p1 += __shfl_xor_sync(0xffffffffu, p1, off);
    }
    if (lane == 0) { logit[2 * w] = p0; logit[2 * w + 1] = p1; }
    __syncthreads();

    if (t < 32) {
        float l = (lane < 16) ? logit[lane] : -1e30f;
        float m = l;
#pragma unroll
        for (int off = 16; off > 0; off >>= 1)
            m = fmaxf(m, __shfl_xor_sync(0xffffffffu, m, off));
        float ex = (lane < 16) ? __expf(l - m) : 0.f;
        float sum = ex;
#pragma unroll
        for (int off = 16; off > 0; off >>= 1)
            sum += __shfl_xor_sync(0xffffffffu, sum, off);
        if (lane < 16) out[gidx * 16 + lane] = l - m - logf(sum);
    }
}

// ---------------- launch ----------------
extern "C" void kernel_launch(void* const* d_in, const int* in_sizes, int n_in,
                              void* d_out, int out_size)
{
    const float* x     = (const float*)d_in[0];
    const int*   ei    = (const int*)  d_in[1];
    const int*   batch = (const int*)  d_in[2];
    const float* lng0  = (const float*)d_in[3];
    const float* lnb0  = (const float*)d_in[4];
    const float* W0    = (const float*)d_in[5];
    const float* as0   = (const float*)d_in[6];
    const float* ad0   = (const float*)d_in[7];
    const float* b0    = (const float*)d_in[8];
    const float* lng1  = (const float*)d_in[9];
    const float* lnb1  = (const float*)d_in[10];
    const float* W1    = (const float*)d_in[11];
    const float* as1   = (const float*)d_in[12];
    const float* ad1   = (const float*)d_in[13];
    const float* b1    = (const float*)d_in[14];
    const float* lngr  = (const float*)d_in[15];
    const float* lnbr  = (const float*)d_in[16];
    const float* Wr    = (const float*)d_in[17];
    float* out = (float*)d_out;

    float *ln_p;
    __nv_bfloat16 *h_p, *wh0_p, *wh1_p;
    cudaGetSymbolAddress((void**)&h_p,    g_h);
    cudaGetSymbolAddress((void**)&ln_p,   g_ln);
    cudaGetSymbolAddress((void**)&wh0_p,  g_Wh0);
    cudaGetSymbolAddress((void**)&wh1_p,  g_Wh1);

    static cudaStream_t s2 = nullptr, s3 = nullptr;
    static cudaEvent_t ev_fork = nullptr, ev_side = nullptr, ev_w0 = nullptr;
    if (!s2) {
        cudaStreamCreateWithFlags(&s2, cudaStreamNonBlocking);
        cudaStreamCreateWithFlags(&s3, cudaStreamNonBlocking);
        cudaEventCreateWithFlags(&ev_fork, cudaEventDisableTiming);
        cudaEventCreateWithFlags(&ev_side, cudaEventDisableTiming);
        cudaEventCreateWithFlags(&ev_w0, cudaEventDisableTiming);
    }

    cudaFuncSetAttribute((const void*)kan_bf16<128, true>,
                         cudaFuncAttributeMaxDynamicSharedMemorySize, SM_BYTES_BF);
    cudaFuncSetAttribute((const void*)kan_bf16<256, false>,
                         cudaFuncAttributeMaxDynamicSharedMemorySize, SM_BYTES_BF);

    const int TPB = 256;
    const int scan_blocks = (NN + 1023) / 1024;
    int warp_blocks = (NN * 32 + TPB - 1) / TPB;   // 6250 (exact)
    int gemm_blocks = (NN + 63) / 64;              // 782

    // ---- fork side streams ----
    cudaEventRecord(ev_fork, 0);
    cudaStreamWaitEvent(s2, ev_fork, 0);
    cudaStreamWaitEvent(s3, ev_fork, 0);

    // s2: CSR build + W1 convert
    clear_kernel<<<(NN + TPB - 1) / TPB, TPB, 0, s2>>>();
    hist_kernel<<<(NE + TPB - 1) / TPB, TPB, 0, s2>>>(ei);
    scan_part1<<<scan_blocks, 256, 0, s2>>>();
    scan_part2<<<1, 64, 0, s2>>>(scan_blocks);
    scan_part3<<<scan_blocks, 1024, 0, s2>>>();
    init_cursor_kernel<<<(NN + TPB - 1) / TPB, TPB, 0, s2>>>();
    scatter_kernel<<<(NE + TPB - 1) / TPB, TPB, 0, s2>>>(ei);
    cvt_w_kernel<<<(256 * 1024 / 4 + TPB - 1) / TPB, TPB, 0, s2>>>(W1, wh1_p, 256 * 1024 / 4);
    cudaEventRecord(ev_side, s2);

    // s3: W0 convert (small; only dependency of kan128 besides x)
    cvt_w_kernel<<<(256 * 512 / 4 + TPB - 1) / TPB, TPB, 0, s3>>>(W0, wh0_p, 256 * 512 / 4);
    cudaEventRecord(ev_w0, s3);

    // ---- main: layer-0 GEMM with fused input LayerNorm ----
    cudaStreamWaitEvent(0, ev_w0, 0);
    kan_bf16<128, true><<<gemm_blocks, TPB, SM_BYTES_BF>>>(x, lng0, lnb0, wh0_p, as0, ad0, h_p);

    // ---- join: aggregate needs CSR (side) + h/alphas (main) ----
    cudaStreamWaitEvent(0, ev_side, 0);
    aggregate_kernel<0><<<warp_blocks, TPB>>>(h_p, b0, lng1, lnb1, batch, ln_p);
    // layer 1
    kan_bf16<256, false><<<gemm_blocks, TPB, SM_BYTES_BF>>>(ln_p, nullptr, nullptr, wh1_p, as1, ad1, h_p);
    aggregate_kernel<1><<<warp_blocks, TPB>>>(h_p, b1, nullptr, nullptr, batch, nullptr);
    // readout
    readout_kernel<<<NG, 256>>>(lngr, lnbr, Wr, out);
}

// round 16
// speedup vs baseline: 1.0337x; 1.0002x over previous
#include <cuda_runtime.h>
#include <cuda_bf16.h>
#include <math.h>
#include <stdint.h>

#define NN 50000
#define NE 800000
#define HC 256
#define NG 64

#define E2M 0.13533528323661270f

// ---------------- device scratch ----------------
__device__ __nv_bfloat16 g_h[(size_t)NN * HC];        // GAT features (bf16)
__device__ __nv_bfloat16 g_bas[(size_t)50048 * 1024]; // layer-1 RBF basis (bf16), zero-init tail
__device__ float g_as[NN * 4];
__device__ float g_ad[NN * 4];
__device__ int   g_cnt[NN];
__device__ int   g_indptr[NN + 1];
__device__ int   g_cursor[NN];
__device__ int   g_ssrc[NE + NN];
__device__ float g_pooled[NG * HC];
__device__ __nv_bfloat16 g_Wh0[512 * 256];    // bf16 W0, [n][k]
__device__ __nv_bfloat16 g_Wh1[1024 * 256];   // bf16 W1, [n][k]
__device__ int   g_bsum[64];
__device__ int   g_boff[64];

__device__ __forceinline__ uint32_t smem_u32(const void* p) {
    uint32_t a;
    asm("{ .reg .u64 t; cvta.to.shared.u64 t, %1; cvt.u32.u64 %0, t; }" : "=r"(a) : "l"(p));
    return a;
}
__device__ __forceinline__ void cp16(void* dst, const void* src) {
    uint32_t d = smem_u32(dst);
    asm volatile("cp.async.cg.shared.global [%0], [%1], 16;" :: "r"(d), "l"(src) : "memory");
}
#define CP_COMMIT() asm volatile("cp.async.commit_group;" ::: "memory")
#define CP_WAIT(n)  asm volatile("cp.async.wait_group %0;" :: "n"(n) : "memory")

__device__ __forceinline__ void ldsm4(unsigned r[4], uint32_t addr) {
    asm volatile("ldmatrix.sync.aligned.m8n8.x4.shared.b16 {%0,%1,%2,%3}, [%4];"
                 : "=r"(r[0]), "=r"(r[1]), "=r"(r[2]), "=r"(r[3]) : "r"(addr));
}
__device__ __forceinline__ void mma_bf16(float c[4], const unsigned a[4], const unsigned b[2]) {
    asm volatile(
        "mma.sync.aligned.m16n8k16.row.col.f32.bf16.bf16.f32 "
        "{%0,%1,%2,%3}, {%4,%5,%6,%7}, {%8,%9}, {%0,%1,%2,%3};\n"
        : "+f"(c[0]), "+f"(c[1]), "+f"(c[2]), "+f"(c[3])
        : "r"(a[0]), "r"(a[1]), "r"(a[2]), "r"(a[3]), "r"(b[0]), "r"(b[1]));
}
__device__ __forceinline__ unsigned pack_bf16x2(float lo, float hi) {
    unsigned u;
    asm("cvt.rn.bf16x2.f32 %0, %1, %2;" : "=r"(u) : "f"(hi), "f"(lo));
    return u;
}
__device__ __forceinline__ float2 bf2_to_f2(unsigned u) {
    __nv_bfloat162 p = *reinterpret_cast<__nv_bfloat162*>(&u);
    return __bfloat1622float2(p);
}

// RBF basis via geometric recurrence
__device__ __forceinline__ void rbf4(float x, float bv[4]) {
    float xp2 = x + 2.f;
    float b0 = __expf(-0.5625f * xp2 * xp2);
    float r  = __expf(fmaf(1.5f, x, 2.f));
    float rg  = r * E2M;
    float rgg = rg * E2M;
    bv[0] = b0;
    bv[1] = b0 * r;
    bv[2] = bv[1] * rg;
    bv[3] = bv[2] * rgg;
}

// ---------------- CSR build ----------------
__global__ void clear_kernel() {
    int i = blockIdx.x * blockDim.x + threadIdx.x;
    if (i < NN) g_cnt[i] = 0;
    if (i < NG * HC) g_pooled[i] = 0.f;
}
__global__ void hist_kernel(const int* __restrict__ ei) {
    int e = blockIdx.x * blockDim.x + threadIdx.x;
    if (e < NE) atomicAdd(&g_cnt[ei[NE + e]], 1);
}
__global__ void scan_part1() {
    __shared__ int wsum[8];
    int t = threadIdx.x;
    int base = blockIdx.x * 1024 + t * 4;
    int v[4];
#pragma unroll
    for (int j = 0; j < 4; j++) {
        int idx = base + j;
        v[j] = (idx < NN) ? (g_cnt[idx] + 1) : 0;
    }
    int s = v[0] + v[1] + v[2] + v[3];
    int lane = t & 31, w = t >> 5;
    int sc = s;
#pragma unroll
    for (int off = 1; off < 32; off <<= 1) {
        int u = __shfl_up_sync(0xffffffffu, sc, off);
        if (lane >= off) sc += u;
    }
    if (lane == 31) wsum[w] = sc;
    __syncthreads();
    if (t < 8) {
        int ws = wsum[t];
#pragma unroll
        for (int off = 1; off < 8; off <<= 1) {
            int u = __shfl_up_sync(0x000000ffu, ws, off);
            if (t >= off) ws += u;
        }
        wsum[t] = ws;
    }
    __syncthreads();
    int excl = sc - s + (w > 0 ? wsum[w - 1] : 0);
#pragma unroll
    for (int j = 0; j < 4; j++) {
        int idx = base + j;
        if (idx < NN) g_indptr[idx] = excl;
        excl += v[j];
    }
    if (t == 255) g_bsum[blockIdx.x] = wsum[7];
}
__global__ void scan_part2(int nb) {
    __shared__ int w0tot;
    int t = threadIdx.x;
    int v = (t < nb) ? g_bsum[t] : 0;
    int lane = t & 31, w = t >> 5;
    int sc = v;
#pragma unroll
    for (int off = 1; off < 32; off <<= 1) {
        int u = __shfl_up_sync(0xffffffffu, sc, off);
        if (lane >= off) sc += u;
    }
    if (t == 31) w0tot = sc;
    __syncthreads();
    int incl = sc + (w == 1 ? w0tot : 0);
    g_boff[t] = incl - v;
    if (t == 63) g_indptr[NN] = incl;
}
__global__ void scan_part3() {
    int i = blockIdx.x * 1024 + threadIdx.x;
    if (i < NN) g_indptr[i] += g_boff[blockIdx.x];
}
__global__ void init_cursor_kernel() {
    int i = blockIdx.x * blockDim.x + threadIdx.x;
    if (i < NN) {
        int p = g_indptr[i];
        g_ssrc[p] = i;
        g_cursor[i] = p + 1;
    }
}
__global__ void scatter_kernel(const int* __restrict__ ei) {
    int e = blockIdx.x * blockDim.x + threadIdx.x;
    if (e < NE) {
        int s = ei[e];
        int d = ei[NE + e];
        int p = atomicAdd(&g_cursor[d], 1);
        g_ssrc[p] = s;
    }
}
__global__ void cvt_w_kernel(const float* __restrict__ W, __nv_bfloat16* __restrict__ out, int n4) {
    int i = blockIdx.x * blockDim.x + threadIdx.x;
    if (i < n4) {
        float4 v = reinterpret_cast<const float4*>(W)[i];
        uint2 o;
        o.x = pack_bf16x2(v.x, v.y);
        o.y = pack_bf16x2(v.z, v.w);
        reinterpret_cast<uint2*>(out)[i] = o;
    }
}

// ---------------- bf16 GEMM: BM=64 BN=256 BK=64 ----------------
// AMODE 0 (layer 0): fused input LayerNorm + in-kernel RBF basis from X (D=128)
// AMODE 1 (layer 1): A tile loaded via cp.async from precomputed bf16 basis (K=1024)
#define STG_BYTES 40960
#define SM_BYTES_BF (2 * STG_BYTES)

template <int D, int AMODE>
__global__ void __launch_bounds__(256, 2)
kan_bf16(const float* __restrict__ X,                 // raw input (AMODE 0)
         const __nv_bfloat16* __restrict__ BAS,       // precomputed basis (AMODE 1)
         const float* __restrict__ lng, const float* __restrict__ lnb,
         const __nv_bfloat16* __restrict__ Wh,
         const float* __restrict__ attS, const float* __restrict__ attD,
         __nv_bfloat16* __restrict__ out)
{
    extern __shared__ char smc[];
    __shared__ float meanS[64], rstdS[64];
    const int K = 4 * D, T = K / 64;
    const int t = threadIdx.x;
    const int wid = t >> 5, lane = t & 31;
    const int wm = wid & 1, wn = wid >> 1;
    const int g4 = lane >> 2, tg = lane & 3;
    const int m0 = blockIdx.x * 64;
    const int head = wn;

    const int arow = t >> 2;
    const int adq  = t & 3;

    // ---- fused LN prologue (AMODE 0 only) ----
    if (AMODE == 0) {
        int rr = m0 + arow;
        if (rr >= NN) rr = NN - 1;
        const float* xr = X + (size_t)rr * D + adq * (D / 4);
        float s = 0.f, ss = 0.f;
#pragma unroll
        for (int i = 0; i < D / 16; i++) {
            float4 v = *reinterpret_cast<const float4*>(xr + i * 4);
            s  += v.x + v.y + v.z + v.w;
            ss += v.x * v.x + v.y * v.y + v.z * v.z + v.w * v.w;
        }
        s  += __shfl_xor_sync(0xffffffffu, s, 1);
        s  += __shfl_xor_sync(0xffffffffu, s, 2);
        ss += __shfl_xor_sync(0xffffffffu, ss, 1);
        ss += __shfl_xor_sync(0xffffffffu, ss, 2);
        if (adq == 0) {
            float mean = s / (float)D;
            meanS[arow] = mean;
            rstdS[arow] = rsqrtf(ss / (float)D - mean * mean + 1e-5f);
        }
        __syncthreads();
    }

    float c[2][8][4];
#pragma unroll
    for (int mt = 0; mt < 2; mt++)
#pragma unroll
        for (int nt = 0; nt < 8; nt++)
#pragma unroll
            for (int i = 0; i < 4; i++) c[mt][nt][i] = 0.f;

#define FILLB(S, KT) do {                                                          \
        char* Ab_ = smc + (S) * STG_BYTES;                                         \
        char* Bb_ = Ab_ + 8192;                                                    \
        _Pragma("unroll")                                                          \
        for (int i = 0; i < 8; i++) {                                              \
            int idx = i * 256 + t;                                                 \
            int row = idx >> 3, ch = idx & 7;                                      \
            const __nv_bfloat16* src = &Wh[(size_t)row * K + (KT) * 64 + ch * 8];  \
            cp16(Bb_ + row * 128 + ((ch ^ (row & 7)) << 4), src);                  \
        }                                                                          \
        if (AMODE == 1) {                                                          \
            _Pragma("unroll")                                                      \
            for (int i = 0; i < 2; i++) {                                          \
                int idx = i * 256 + t;                                             \
                int row = idx >> 3, ch = idx & 7;                                  \
                const __nv_bfloat16* src =                                         \
                    &BAS[(size_t)(m0 + row) * 1024 + (KT) * 64 + ch * 8];          \
                cp16(Ab_ + row * 128 + ((ch ^ (row & 7)) << 4), src);              \
            }                                                                      \
            CP_COMMIT();                                                           \
        } else {                                                                   \
            CP_COMMIT();                                                           \
            int d0 = (KT) * 16 + adq * 4;                                          \
            int rr = m0 + arow;                                                    \
            if (rr >= NN) rr = NN - 1;                                             \
            const float* lp = &X[(size_t)rr * D + d0];                             \
            float4 lv = *reinterpret_cast<const float4*>(lp);                      \
            float dv[4] = {lv.x, lv.y, lv.z, lv.w};                                \
            float mean = meanS[arow], rstd = rstdS[arow];                          \
            float4 gg = *reinterpret_cast<const float4*>(&lng[d0]);                \
            float4 bb = *reinterpret_cast<const float4*>(&lnb[d0]);                \
            dv[0] = (dv[0] - mean) * rstd * gg.x + bb.x;                           \
            dv[1] = (dv[1] - mean) * rstd * gg.y + bb.y;                           \
            dv[2] = (dv[2] - mean) * rstd * gg.z + bb.z;                           \
            dv[3] = (dv[3] - mean) * rstd * gg.w + bb.w;                           \
            unsigned pk[8];                                                        \
            _Pragma("unroll")                                                      \
            for (int j = 0; j < 4; j++) {                                          \
                float bv[4];                                                       \
                rbf4(dv[j], bv);                                                   \
                pk[j * 2]     = pack_bf16x2(bv[0], bv[1]);                         \
                pk[j * 2 + 1] = pack_bf16x2(bv[2], bv[3]);                         \
            }                                                                      \
            _Pragma("unroll")                                                      \
            for (int q = 0; q < 2; q++) {                                          \
                int cc = adq * 2 + q;                                              \
                uint4 u = make_uint4(pk[q * 4], pk[q * 4 + 1],                     \
                                     pk[q * 4 + 2], pk[q * 4 + 3]);                \
                *reinterpret_cast<uint4*>(Ab_ + arow * 128 +                        \
                    ((cc ^ (arow & 7)) << 4)) = u;                                 \
            }                                                                      \
        }                                                                          \
    } while (0)

    FILLB(0, 0);

    for (int kt = 0; kt < T; kt++) {
        const int s = kt & 1;
        if (kt + 1 < T) {
            FILLB(s ^ 1, kt + 1);
            CP_WAIT(1);
        } else {
            CP_WAIT(0);
        }
        __syncthreads();
        const char* Ab = smc + s * STG_BYTES;
        const char* Bb = Ab + 8192;
#pragma unroll
        for (int k16 = 0; k16 < 4; k16++) {
            unsigned a[2][4];
#pragma unroll
            for (int mt = 0; mt < 2; mt++) {
                int mrow = wm * 32 + mt * 16 + ((lane >> 3) & 1) * 8 + (lane & 7);
                int c16 = k16 * 2 + (lane >> 4);
                ldsm4(a[mt], smem_u32(Ab + mrow * 128 + ((c16 ^ (mrow & 7)) << 4)));
            }
#pragma unroll
            for (int ntq = 0; ntq < 4; ntq++) {
                int nrow = wn * 64 + (ntq * 2 + (lane >> 4)) * 8 + (lane & 7);
                int c16 = k16 * 2 + ((lane >> 3) & 1);
                unsigned b[4];
                ldsm4(b, smem_u32(Bb + nrow * 128 + ((c16 ^ (nrow & 7)) << 4)));
                mma_bf16(c[0][ntq * 2],     a[0], b);
                mma_bf16(c[0][ntq * 2 + 1], a[0], b + 2);
                mma_bf16(c[1][ntq * 2],     a[1], b);
                mma_bf16(c[1][ntq * 2 + 1], a[1], b + 2);
            }
        }
        __syncthreads();
    }

    // ---- epilogue: fused alphas (warp = one head) + bf16 store of h ----
    float sa[2][2] = {{0.f,0.f},{0.f,0.f}};
    float sd[2][2] = {{0.f,0.f},{0.f,0.f}};
#pragma unroll
    for (int nt = 0; nt < 8; nt++) {
        int cidx = head * 64 + nt * 8 + tg * 2;
        float2 aS = *reinterpret_cast<const float2*>(&attS[cidx]);
        float2 aD = *reinterpret_cast<const float2*>(&attD[cidx]);
#pragma unroll
        for (int mt = 0; mt < 2; mt++) {
            sa[mt][0] += c[mt][nt][0] * aS.x + c[mt][nt][1] * aS.y;
            sa[mt][1] += c[mt][nt][2] * aS.x + c[mt][nt][3] * aS.y;
            sd[mt][0] += c[mt][nt][0] * aD.x + c[mt][nt][1] * aD.y;
            sd[mt][1] += c[mt][nt][2] * aD.x + c[mt][nt][3] * aD.y;
        }
    }
#pragma unroll
    for (int mt = 0; mt < 2; mt++)
#pragma unroll
        for (int hh = 0; hh < 2; hh++) {
            sa[mt][hh] += __shfl_xor_sync(0xffffffffu, sa[mt][hh], 1);
            sa[mt][hh] += __shfl_xor_sync(0xffffffffu, sa[mt][hh], 2);
            sd[mt][hh] += __shfl_xor_sync(0xffffffffu, sd[mt][hh], 1);
            sd[mt][hh] += __shfl_xor_sync(0xffffffffu, sd[mt][hh], 2);
        }

#pragma unroll
    for (int mt = 0; mt < 2; mt++) {
        int r0 = m0 + wm * 32 + mt * 16 + g4;
#pragma unroll
        for (int nt = 0; nt < 8; nt++) {
            int nc = wn * 64 + nt * 8 + tg * 2;
            if (r0 < NN)
                *reinterpret_cast<unsigned*>(&out[(size_t)r0 * 256 + nc]) =
                    pack_bf16x2(c[mt][nt][0], c[mt][nt][1]);
            if (r0 + 8 < NN)
                *reinterpret_cast<unsigned*>(&out[(size_t)(r0 + 8) * 256 + nc]) =
                    pack_bf16x2(c[mt][nt][2], c[mt][nt][3]);
        }
        if (tg == 0) {
            if (r0 < NN)     { g_as[r0 * 4 + head]       = sa[mt][0]; g_ad[r0 * 4 + head]       = sd[mt][0]; }
            if (r0 + 8 < NN) { g_as[(r0 + 8) * 4 + head] = sa[mt][1]; g_ad[(r0 + 8) * 4 + head] = sd[mt][1]; }
        }
    }
#undef FILLB
}

// ---------------- edge aggregation: SINGLE PASS, MLP-4 ----------------
// MODE 0: silu -> LN -> RBF basis (bf16) stored to g_bas (feeds layer-1 GEMM)
// MODE 1: silu -> fused global_add_pool
__device__ __forceinline__ float leaky(float x) { return x > 0.f ? x : 0.2f * x; }

template <int MODE>
__global__ void aggregate_kernel(const __nv_bfloat16* __restrict__ h,
                                 const float* __restrict__ bias,
                                 const float* __restrict__ lng,
                                 const float* __restrict__ lnb,
                                 const int* __restrict__ batch,
                                 __nv_bfloat16* __restrict__ bas_out)
{
    __shared__ float sp[256];
    __shared__ int bg_s;
    int wid = threadIdx.x >> 5;
    int lane = threadIdx.x & 31;
    int i = blockIdx.x * 8 + wid;   // grid covers exactly NN warps

    int my_g = 0;
    if (MODE == 1) {
        my_g = batch[i];
        if (threadIdx.x == 0) bg_s = my_g;
        sp[threadIdx.x] = 0.f;
        __syncthreads();
    }

    int p0 = g_indptr[i];
    int p1 = g_indptr[i + 1];
    int head = lane >> 3;
    float adh = g_ad[i * 4 + head];

    float acc[8];
#pragma unroll
    for (int k = 0; k < 8; k++) acc[k] = 0.f;
    float den = 0.f;

#define ACC4(U, W) \
    f = bf2_to_f2(U.x); acc[0] += W * f.x; acc[1] += W * f.y; \
    f = bf2_to_f2(U.y); acc[2] += W * f.x; acc[3] += W * f.y; \
    f = bf2_to_f2(U.z); acc[4] += W * f.x; acc[5] += W * f.y; \
    f = bf2_to_f2(U.w); acc[6] += W * f.x; acc[7] += W * f.y;

    int j = p0;
    for (; j + 3 < p1; j += 4) {
        int s0 = g_ssrc[j], s1 = g_ssrc[j + 1], s2 = g_ssrc[j + 2], s3 = g_ssrc[j + 3];
        uint4 u0 = *reinterpret_cast<const uint4*>(h + (size_t)s0 * 256 + lane * 8);
        uint4 u1 = *reinterpret_cast<const uint4*>(h + (size_t)s1 * 256 + lane * 8);
        uint4 u2 = *reinterpret_cast<const uint4*>(h + (size_t)s2 * 256 + lane * 8);
        uint4 u3 = *reinterpret_cast<const uint4*>(h + (size_t)s3 * 256 + lane * 8);
        float a0 = g_as[s0 * 4 + head], a1 = g_as[s1 * 4 + head];
        float a2 = g_as[s2 * 4 + head], a3 = g_as[s3 * 4 + head];
        float w0 = __expf(leaky(a0 + adh));
        float w1 = __expf(leaky(a1 + adh));
        float w2 = __expf(leaky(a2 + adh));
        float w3 = __expf(leaky(a3 + adh));
        den += (w0 + w1) + (w2 + w3);
        float2 f;
        ACC4(u0, w0) ACC4(u1, w1) ACC4(u2, w2) ACC4(u3, w3)
    }
    for (; j < p1; j++) {
        int s = g_ssrc[j];
        uint4 u = *reinterpret_cast<const uint4*>(h + (size_t)s * 256 + lane * 8);
        float w = __expf(leaky(g_as[s * 4 + head] + adh));
        den += w;
        float2 f;
        ACC4(u, w)
    }
#undef ACC4

    float inv = 1.f / den;
    int cb = lane * 8;
    float r[8];
#pragma unroll
    for (int k = 0; k < 8; k++) {
        float v = acc[k] * inv + bias[cb + k];
        r[k] = v / (1.f + __expf(-v));   // silu
    }

    if (MODE == 0) {
        float s = 0.f, ss = 0.f;
#pragma unroll
        for (int k = 0; k < 8; k++) { s += r[k]; ss += r[k] * r[k]; }
#pragma unroll
        for (int off = 16; off > 0; off >>= 1) {
            s  += __shfl_xor_sync(0xffffffffu, s, off);
            ss += __shfl_xor_sync(0xffffffffu, ss, off);
        }
        float mean = s / 256.f;
        float rstd = rsqrtf(ss / 256.f - mean * mean + 1e-5f);
        float4 g0 = *reinterpret_cast<const float4*>(&lng[cb]);
        float4 g1 = *reinterpret_cast<const float4*>(&lng[cb + 4]);
        float4 b0 = *reinterpret_cast<const float4*>(&lnb[cb]);
        float4 b1 = *reinterpret_cast<const float4*>(&lnb[cb + 4]);
        float o[8];
        o[0] = (r[0]-mean)*rstd*g0.x + b0.x; o[1] = (r[1]-mean)*rstd*g0.y + b0.y;
        o[2] = (r[2]-mean)*rstd*g0.z + b0.z; o[3] = (r[3]-mean)*rstd*g0.w + b0.w;
        o[4] = (r[4]-mean)*rstd*g1.x + b1.x; o[5] = (r[5]-mean)*rstd*g1.y + b1.y;
        o[6] = (r[6]-mean)*rstd*g1.z + b1.z; o[7] = (r[7]-mean)*rstd*g1.w + b1.w;
        // RBF basis -> bf16 store (32 values = 64B per lane, contiguous)
        unsigned pk[16];
#pragma unroll
        for (int k = 0; k < 8; k++) {
            float bv[4];
            rbf4(o[k], bv);
            pk[k * 2]     = pack_bf16x2(bv[0], bv[1]);
            pk[k * 2 + 1] = pack_bf16x2(bv[2], bv[3]);
        }
        uint4* bp = reinterpret_cast<uint4*>(&bas_out[(size_t)i * 1024 + cb * 4]);
        bp[0] = make_uint4(pk[0],  pk[1],  pk[2],  pk[3]);
        bp[1] = make_uint4(pk[4],  pk[5],  pk[6],  pk[7]);
        bp[2] = make_uint4(pk[8],  pk[9],  pk[10], pk[11]);
        bp[3] = make_uint4(pk[12], pk[13], pk[14], pk[15]);
    } else {
        int bg = bg_s;
        if (my_g == bg) {
#pragma unroll
            for (int k = 0; k < 8; k++) atomicAdd(&sp[cb + k], r[k]);
        } else {
#pragma unroll
            for (int k = 0; k < 8; k++) atomicAdd(&g_pooled[my_g * 256 + cb + k], r[k]);
        }
        __syncthreads();
        atomicAdd(&g_pooled[bg * 256 + threadIdx.x], sp[threadIdx.x]);
    }
}

// ---------------- readout ----------------
__global__ void readout_kernel(const float* __restrict__ lng, const float* __restrict__ lnb,
                               const float* __restrict__ Wr, float* __restrict__ out)
{
    __shared__ float bas[1024];
    __shared__ float red[16];
    __shared__ float logit[16];
    __shared__ float mean_s, rstd_s;
    int gidx = blockIdx.x, t = threadIdx.x;
    int lane = t & 31, w = t >> 5;

    float v = g_pooled[gidx * 256 + t];
    float s = v, ss = v * v;
#pragma unroll
    for (int off = 16; off > 0; off >>= 1) {
        s  += __shfl_xor_sync(0xffffffffu, s, off);
        ss += __shfl_xor_sync(0xffffffffu, ss, off);
    }
    if (lane == 0) { red[w] = s; red[8 + w] = ss; }
    __syncthreads();
    if (t == 0) {
        float S = 0.f, SS = 0.f;
        for (int k = 0; k < 8; k++) { S += red[k]; SS += red[8 + k]; }
        float mean = S / 256.f;
        float var  = SS / 256.f - mean * mean;
        mean_s = mean; rstd_s = rsqrtf(var + 1e-5f);
    }
    __syncthreads();
    float ln = (v - mean_s) * rstd_s * lng[t] + lnb[t];
    {
        float bv[4];
        rbf4(ln, bv);
        bas[t * 4 + 0] = bv[0];
        bas[t * 4 + 1] = bv[1];
        bas[t * 4 + 2] = bv[2];
        bas[t * 4 + 3] = bv[3];
    }
    __syncthreads();

    float p0 = 0.f, p1 = 0.f;
    const float* w0 = Wr + (size_t)(2 * w) * 1024;
    const float* w1 = w0 + 1024;
    for (int k = lane; k < 1024; k += 32) {
        float bv = bas[k];
        p0 += bv * w0[k];
        p1 += bv * w1[k];
    }
#pragma unroll
    for (int off = 16; off > 0; off >>= 1) {
        p0 += __shfl_xor_sync(0xffffffffu, p0, off);
        p1 += __shfl_xor_sync(0xffffffffu, p1, off);
    }
    if (lane == 0) { logit[2 * w] = p0; logit[2 * w + 1] = p1; }
    __syncthreads();

    if (t < 32) {
        float l = (lane < 16) ? logit[lane] : -1e30f;
        float m = l;
#pragma unroll
        for (int off = 16; off > 0; off >>= 1)
            m = fmaxf(m, __shfl_xor_sync(0xffffffffu, m, off));
        float ex = (lane < 16) ? __expf(l - m) : 0.f;
        float sum = ex;
#pragma unroll
        for (int off = 16; off > 0; off >>= 1)
            sum += __shfl_xor_sync(0xffffffffu, sum, off);
        if (lane < 16) out[gidx * 16 + lane] = l - m - logf(sum);
    }
}

// ---------------- launch ----------------
extern "C" void kernel_launch(void* const* d_in, const int* in_sizes, int n_in,
                              void* d_out, int out_size)
{
    const float* x     = (const float*)d_in[0];
    const int*   ei    = (const int*)  d_in[1];
    const int*   batch = (const int*)  d_in[2];
    const float* lng0  = (const float*)d_in[3];
    const float* lnb0  = (const float*)d_in[4];
    const float* W0    = (const float*)d_in[5];
    const float* as0   = (const float*)d_in[6];
    const float* ad0   = (const float*)d_in[7];
    const float* b0    = (const float*)d_in[8];
    const float* lng1  = (const float*)d_in[9];
    const float* lnb1  = (const float*)d_in[10];
    const float* W1    = (const float*)d_in[11];
    const float* as1   = (const float*)d_in[12];
    const float* ad1   = (const float*)d_in[13];
    const float* b1    = (const float*)d_in[14];
    const float* lngr  = (const float*)d_in[15];
    const float* lnbr  = (const float*)d_in[16];
    const float* Wr    = (const float*)d_in[17];
    float* out = (float*)d_out;

    __nv_bfloat16 *h_p, *bas_p, *wh0_p, *wh1_p;
    cudaGetSymbolAddress((void**)&h_p,    g_h);
    cudaGetSymbolAddress((void**)&bas_p,  g_bas);
    cudaGetSymbolAddress((void**)&wh0_p,  g_Wh0);
    cudaGetSymbolAddress((void**)&wh1_p,  g_Wh1);

    static cudaStream_t s2 = nullptr, s3 = nullptr;
    static cudaEvent_t ev_fork = nullptr, ev_side = nullptr, ev_w0 = nullptr;
    if (!s2) {
        cudaStreamCreateWithFlags(&s2, cudaStreamNonBlocking);
        cudaStreamCreateWithFlags(&s3, cudaStreamNonBlocking);
        cudaEventCreateWithFlags(&ev_fork, cudaEventDisableTiming);
        cudaEventCreateWithFlags(&ev_side, cudaEventDisableTiming);
        cudaEventCreateWithFlags(&ev_w0, cudaEventDisableTiming);
    }

    cudaFuncSetAttribute((const void*)kan_bf16<128, 0>,
                         cudaFuncAttributeMaxDynamicSharedMemorySize, SM_BYTES_BF);
    cudaFuncSetAttribute((const void*)kan_bf16<256, 1>,
                         cudaFuncAttributeMaxDynamicSharedMemorySize, SM_BYTES_BF);

    const int TPB = 256;
    const int scan_blocks = (NN + 1023) / 1024;
    int warp_blocks = (NN * 32 + TPB - 1) / TPB;   // 6250 (exact)
    int gemm_blocks = (NN + 63) / 64;              // 782

    // ---- fork side streams ----
    cudaEventRecord(ev_fork, 0);
    cudaStreamWaitEvent(s2, ev_fork, 0);
    cudaStreamWaitEvent(s3, ev_fork, 0);

    // s2: CSR build + W1 convert
    clear_kernel<<<(NN + TPB - 1) / TPB, TPB, 0, s2>>>();
    hist_kernel<<<(NE + TPB - 1) / TPB, TPB, 0, s2>>>(ei);
    scan_part1<<<scan_blocks, 256, 0, s2>>>();
    scan_part2<<<1, 64, 0, s2>>>(scan_blocks);
    scan_part3<<<scan_blocks, 1024, 0, s2>>>();
    init_cursor_kernel<<<(NN + TPB - 1) / TPB, TPB, 0, s2>>>();
    scatter_kernel<<<(NE + TPB - 1) / TPB, TPB, 0, s2>>>(ei);
    cvt_w_kernel<<<(256 * 1024 / 4 + TPB - 1) / TPB, TPB, 0, s2>>>(W1, wh1_p, 256 * 1024 / 4);
    cudaEventRecord(ev_side, s2);

    // s3: W0 convert
    cvt_w_kernel<<<(256 * 512 / 4 + TPB - 1) / TPB, TPB, 0, s3>>>(W0, wh0_p, 256 * 512 / 4);
    cudaEventRecord(ev_w0, s3);

    // ---- main: layer-0 GEMM with fused input LayerNorm ----
    cudaStreamWaitEvent(0, ev_w0, 0);
    kan_bf16<128, 0><<<gemm_blocks, TPB, SM_BYTES_BF>>>(x, nullptr, lng0, lnb0, wh0_p, as0, ad0, h_p);

    // ---- join: aggregate needs CSR (side) + h/alphas (main) ----
    cudaStreamWaitEvent(0, ev_side, 0);
    aggregate_kernel<0><<<warp_blocks, TPB>>>(h_p, b0, lng1, lnb1, batch, bas_p);
    // layer 1 (A tile streamed from precomputed basis)
    kan_bf16<256, 1><<<gemm_blocks, TPB, SM_BYTES_BF>>>(nullptr, bas_p, nullptr, nullptr, wh1_p, as1, ad1, h_p);
    aggregate_kernel<1><<<warp_blocks, TPB>>>(h_p, b1, nullptr, nullptr, batch, nullptr);
    // readout
    readout_kernel<<<NG, 256>>>(lngr, lnbr, Wr, out);
}

// round 17
// speedup vs baseline: 1.0404x; 1.0065x over previous
#include <cuda_runtime.h>
#include <cuda_bf16.h>
#include <math.h>
#include <stdint.h>

#define NN 50000
#define NE 800000
#define HC 256
#define NG 64

#define E2M 0.13533528323661270f

// ---------------- device scratch ----------------
__device__ __nv_bfloat16 g_h[(size_t)NN * HC];        // GAT features (bf16)
__device__ __nv_bfloat16 g_bas[(size_t)50048 * 1024]; // layer-1 RBF basis (bf16), zero-init tail
__device__ float g_as[NN * 4];
__device__ float g_ad[NN * 4];
__device__ int   g_cnt[NN];                            // zeroed at load; self-restoring per replay
__device__ int   g_indptr[NN + 1];
__device__ int   g_cursor[NN];
__device__ int   g_ssrc[NE + NN];
__device__ float g_pooled[NG * HC];
__device__ __nv_bfloat16 g_Wh0[512 * 256];    // bf16 W0, [n][k]
__device__ __nv_bfloat16 g_Wh1[1024 * 256];   // bf16 W1, [n][k]
__device__ int   g_bsum[64];
__device__ int   g_boff[64];

__device__ __forceinline__ uint32_t smem_u32(const void* p) {
    uint32_t a;
    asm("{ .reg .u64 t; cvta.to.shared.u64 t, %1; cvt.u32.u64 %0, t; }" : "=r"(a) : "l"(p));
    return a;
}
__device__ __forceinline__ void cp16(void* dst, const void* src) {
    uint32_t d = smem_u32(dst);
    asm volatile("cp.async.cg.shared.global [%0], [%1], 16;" :: "r"(d), "l"(src) : "memory");
}
#define CP_COMMIT() asm volatile("cp.async.commit_group;" ::: "memory")
#define CP_WAIT(n)  asm volatile("cp.async.wait_group %0;" :: "n"(n) : "memory")

__device__ __forceinline__ void ldsm4(unsigned r[4], uint32_t addr) {
    asm volatile("ldmatrix.sync.aligned.m8n8.x4.shared.b16 {%0,%1,%2,%3}, [%4];"
                 : "=r"(r[0]), "=r"(r[1]), "=r"(r[2]), "=r"(r[3]) : "r"(addr));
}
__device__ __forceinline__ void mma_bf16(float c[4], const unsigned a[4], const unsigned b[2]) {
    asm volatile(
        "mma.sync.aligned.m16n8k16.row.col.f32.bf16.bf16.f32 "
        "{%0,%1,%2,%3}, {%4,%5,%6,%7}, {%8,%9}, {%0,%1,%2,%3};\n"
        : "+f"(c[0]), "+f"(c[1]), "+f"(c[2]), "+f"(c[3])
        : "r"(a[0]), "r"(a[1]), "r"(a[2]), "r"(a[3]), "r"(b[0]), "r"(b[1]));
}
__device__ __forceinline__ unsigned pack_bf16x2(float lo, float hi) {
    unsigned u;
    asm("cvt.rn.bf16x2.f32 %0, %1, %2;" : "=r"(u) : "f"(hi), "f"(lo));
    return u;
}
__device__ __forceinline__ float2 bf2_to_f2(unsigned u) {
    __nv_bfloat162 p = *reinterpret_cast<__nv_bfloat162*>(&u);
    return __bfloat1622float2(p);
}

// RBF basis via geometric recurrence
__device__ __forceinline__ void rbf4(float x, float bv[4]) {
    float xp2 = x + 2.f;
    float b0 = __expf(-0.5625f * xp2 * xp2);
    float r  = __expf(fmaf(1.5f, x, 2.f));
    float rg  = r * E2M;
    float rgg = rg * E2M;
    bv[0] = b0;
    bv[1] = b0 * r;
    bv[2] = bv[1] * rg;
    bv[3] = bv[2] * rgg;
}

// ---------------- CSR build ----------------
__global__ void hist_kernel(const int* __restrict__ ei) {
    int e = blockIdx.x * blockDim.x + threadIdx.x;
    if (e < NE) atomicAdd(&g_cnt[ei[NE + e]], 1);
}
// reads cnt(+1 self loop), zeroes cnt for next graph replay
__global__ void scan_part1() {
    __shared__ int wsum[8];
    int t = threadIdx.x;
    int base = blockIdx.x * 1024 + t * 4;
    int v[4];
#pragma unroll
    for (int j = 0; j < 4; j++) {
        int idx = base + j;
        if (idx < NN) {
            v[j] = g_cnt[idx] + 1;
            g_cnt[idx] = 0;          // self-restore for replay
        } else v[j] = 0;
    }
    int s = v[0] + v[1] + v[2] + v[3];
    int lane = t & 31, w = t >> 5;
    int sc = s;
#pragma unroll
    for (int off = 1; off < 32; off <<= 1) {
        int u = __shfl_up_sync(0xffffffffu, sc, off);
        if (lane >= off) sc += u;
    }
    if (lane == 31) wsum[w] = sc;
    __syncthreads();
    if (t < 8) {
        int ws = wsum[t];
#pragma unroll
        for (int off = 1; off < 8; off <<= 1) {
            int u = __shfl_up_sync(0x000000ffu, ws, off);
            if (t >= off) ws += u;
        }
        wsum[t] = ws;
    }
    __syncthreads();
    int excl = sc - s + (w > 0 ? wsum[w - 1] : 0);
#pragma unroll
    for (int j = 0; j < 4; j++) {
        int idx = base + j;
        if (idx < NN) g_indptr[idx] = excl;
        excl += v[j];
    }
    if (t == 255) g_bsum[blockIdx.x] = wsum[7];
}
__global__ void scan_part2(int nb) {
    __shared__ int w0tot;
    int t = threadIdx.x;
    int v = (t < nb) ? g_bsum[t] : 0;
    int lane = t & 31, w = t >> 5;
    int sc = v;
#pragma unroll
    for (int off = 1; off < 32; off <<= 1) {
        int u = __shfl_up_sync(0xffffffffu, sc, off);
        if (lane >= off) sc += u;
    }
    if (t == 31) w0tot = sc;
    __syncthreads();
    int incl = sc + (w == 1 ? w0tot : 0);
    g_boff[t] = incl - v;
    if (t == 63) g_indptr[NN] = incl;
}
// final indptr + self-loop seed + cursor init + pooled zero
__global__ void scan_part3() {
    int i = blockIdx.x * 1024 + threadIdx.x;
    if (i < NN) {
        int p = g_indptr[i] + g_boff[blockIdx.x];
        g_indptr[i] = p;
        g_ssrc[p] = i;
        g_cursor[i] = p + 1;
    }
    if (i < NG * HC) g_pooled[i] = 0.f;
}
__global__ void scatter_kernel(const int* __restrict__ ei) {
    int e = blockIdx.x * blockDim.x + threadIdx.x;
    if (e < NE) {
        int s = ei[e];
        int d = ei[NE + e];
        int p = atomicAdd(&g_cursor[d], 1);
        g_ssrc[p] = s;
    }
}
__global__ void cvt_w_kernel(const float* __restrict__ W, __nv_bfloat16* __restrict__ out, int n4) {
    int i = blockIdx.x * blockDim.x + threadIdx.x;
    if (i < n4) {
        float4 v = reinterpret_cast<const float4*>(W)[i];
        uint2 o;
        o.x = pack_bf16x2(v.x, v.y);
        o.y = pack_bf16x2(v.z, v.w);
        reinterpret_cast<uint2*>(out)[i] = o;
    }
}

// ---------------- bf16 GEMM: BM=64 BN=256 BK=64 ----------------
// AMODE 0 (layer 0): fused input LayerNorm + in-kernel RBF basis from X (D=128)
// AMODE 1 (layer 1): A tile loaded via cp.async from precomputed bf16 basis (K=1024)
#define STG_BYTES 40960
#define SM_BYTES_BF (2 * STG_BYTES)

template <int D, int AMODE>
__global__ void __launch_bounds__(256, 2)
kan_bf16(const float* __restrict__ X,
         const __nv_bfloat16* __restrict__ BAS,
         const float* __restrict__ lng, const float* __restrict__ lnb,
         const __nv_bfloat16* __restrict__ Wh,
         const float* __restrict__ attS, const float* __restrict__ attD,
         __nv_bfloat16* __restrict__ out)
{
    extern __shared__ char smc[];
    __shared__ float meanS[64], rstdS[64];
    const int K = 4 * D, T = K / 64;
    const int t = threadIdx.x;
    const int wid = t >> 5, lane = t & 31;
    const int wm = wid & 1, wn = wid >> 1;
    const int g4 = lane >> 2, tg = lane & 3;
    const int m0 = blockIdx.x * 64;
    const int head = wn;

    const int arow = t >> 2;
    const int adq  = t & 3;

    if (AMODE == 0) {
        int rr = m0 + arow;
        if (rr >= NN) rr = NN - 1;
        const float* xr = X + (size_t)rr * D + adq * (D / 4);
        float s = 0.f, ss = 0.f;
#pragma unroll
        for (int i = 0; i < D / 16; i++) {
            float4 v = *reinterpret_cast<const float4*>(xr + i * 4);
            s  += v.x + v.y + v.z + v.w;
            ss += v.x * v.x + v.y * v.y + v.z * v.z + v.w * v.w;
        }
        s  += __shfl_xor_sync(0xffffffffu, s, 1);
        s  += __shfl_xor_sync(0xffffffffu, s, 2);
        ss += __shfl_xor_sync(0xffffffffu, ss, 1);
        ss += __shfl_xor_sync(0xffffffffu, ss, 2);
        if (adq == 0) {
            float mean = s / (float)D;
            meanS[arow] = mean;
            rstdS[arow] = rsqrtf(ss / (float)D - mean * mean + 1e-5f);
        }
        __syncthreads();
    }

    float c[2][8][4];
#pragma unroll
    for (int mt = 0; mt < 2; mt++)
#pragma unroll
        for (int nt = 0; nt < 8; nt++)
#pragma unroll
            for (int i = 0; i < 4; i++) c[mt][nt][i] = 0.f;

#define FILLB(S, KT) do {                                                          \
        char* Ab_ = smc + (S) * STG_BYTES;                                         \
        char* Bb_ = Ab_ + 8192;                                                    \
        _Pragma("unroll")                                                          \
        for (int i = 0; i < 8; i++) {                                              \
            int idx = i * 256 + t;                                                 \
            int row = idx >> 3, ch = idx & 7;                                      \
            const __nv_bfloat16* src = &Wh[(size_t)row * K + (KT) * 64 + ch * 8];  \
            cp16(Bb_ + row * 128 + ((ch ^ (row & 7)) << 4), src);                  \
        }                                                                          \
        if (AMODE == 1) {                                                          \
            _Pragma("unroll")                                                      \
            for (int i = 0; i < 2; i++) {                                          \
                int idx = i * 256 + t;                                             \
                int row = idx >> 3, ch = idx & 7;                                  \
                const __nv_bfloat16* src =                                         \
                    &BAS[(size_t)(m0 + row) * 1024 + (KT) * 64 + ch * 8];          \
                cp16(Ab_ + row * 128 + ((ch ^ (row & 7)) << 4), src);              \
            }                                                                      \
            CP_COMMIT();                                                           \
        } else {                                                                   \
            CP_COMMIT();                                                           \
            int d0 = (KT) * 16 + adq * 4;                                          \
            int rr = m0 + arow;                                                    \
            if (rr >= NN) rr = NN - 1;                                             \
            const float* lp = &X[(size_t)rr * D + d0];                             \
            float4 lv = *reinterpret_cast<const float4*>(lp);                      \
            float dv[4] = {lv.x, lv.y, lv.z, lv.w};                                \
            float mean = meanS[arow], rstd = rstdS[arow];                          \
            float4 gg = *reinterpret_cast<const float4*>(&lng[d0]);                \
            float4 bb = *reinterpret_cast<const float4*>(&lnb[d0]);                \
            dv[0] = (dv[0] - mean) * rstd * gg.x + bb.x;                           \
            dv[1] = (dv[1] - mean) * rstd * gg.y + bb.y;                           \
            dv[2] = (dv[2] - mean) * rstd * gg.z + bb.z;                           \
            dv[3] = (dv[3] - mean) * rstd * gg.w + bb.w;                           \
            unsigned pk[8];                                                        \
            _Pragma("unroll")                                                      \
            for (int j = 0; j < 4; j++) {                                          \
                float bv[4];                                                       \
                rbf4(dv[j], bv);                                                   \
                pk[j * 2]     = pack_bf16x2(bv[0], bv[1]);                         \
                pk[j * 2 + 1] = pack_bf16x2(bv[2], bv[3]);                         \
            }                                                                      \
            _Pragma("unroll")                                                      \
            for (int q = 0; q < 2; q++) {                                          \
                int cc = adq * 2 + q;                                              \
                uint4 u = make_uint4(pk[q * 4], pk[q * 4 + 1],                     \
                                     pk[q * 4 + 2], pk[q * 4 + 3]);                \
                *reinterpret_cast<uint4*>(Ab_ + arow * 128 +                        \
                    ((cc ^ (arow & 7)) << 4)) = u;                                 \
            }                                                                      \
        }                                                                          \
    } while (0)

    FILLB(0, 0);

    for (int kt = 0; kt < T; kt++) {
        const int s = kt & 1;
        if (kt + 1 < T) {
            FILLB(s ^ 1, kt + 1);
            CP_WAIT(1);
        } else {
            CP_WAIT(0);
        }
        __syncthreads();
        const char* Ab = smc + s * STG_BYTES;
        const char* Bb = Ab + 8192;
#pragma unroll
        for (int k16 = 0; k16 < 4; k16++) {
            unsigned a[2][4];
#pragma unroll
            for (int mt = 0; mt < 2; mt++) {
                int mrow = wm * 32 + mt * 16 + ((lane >> 3) & 1) * 8 + (lane & 7);
                int c16 = k16 * 2 + (lane >> 4);
                ldsm4(a[mt], smem_u32(Ab + mrow * 128 + ((c16 ^ (mrow & 7)) << 4)));
            }
#pragma unroll
            for (int ntq = 0; ntq < 4; ntq++) {
                int nrow = wn * 64 + (ntq * 2 + (lane >> 4)) * 8 + (lane & 7);
                int c16 = k16 * 2 + ((lane >> 3) & 1);
                unsigned b[4];
                ldsm4(b, smem_u32(Bb + nrow * 128 + ((c16 ^ (nrow & 7)) << 4)));
                mma_bf16(c[0][ntq * 2],     a[0], b);
                mma_bf16(c[0][ntq * 2 + 1], a[0], b + 2);
                mma_bf16(c[1][ntq * 2],     a[1], b);
                mma_bf16(c[1][ntq * 2 + 1], a[1], b + 2);
            }
        }
        __syncthreads();
    }

    // ---- epilogue: fused alphas (warp = one head) + bf16 store of h ----
    float sa[2][2] = {{0.f,0.f},{0.f,0.f}};
    float sd[2][2] = {{0.f,0.f},{0.f,0.f}};
#pragma unroll
    for (int nt = 0; nt < 8; nt++) {
        int cidx = head * 64 + nt * 8 + tg * 2;
        float2 aS = *reinterpret_cast<const float2*>(&attS[cidx]);
        float2 aD = *reinterpret_cast<const float2*>(&attD[cidx]);
#pragma unroll
        for (int mt = 0; mt < 2; mt++) {
            sa[mt][0] += c[mt][nt][0] * aS.x + c[mt][nt][1] * aS.y;
            sa[mt][1] += c[mt][nt][2] * aS.x + c[mt][nt][3] * aS.y;
            sd[mt][0] += c[mt][nt][0] * aD.x + c[mt][nt][1] * aD.y;
            sd[mt][1] += c[mt][nt][2] * aD.x + c[mt][nt][3] * aD.y;
        }
    }
#pragma unroll
    for (int mt = 0; mt < 2; mt++)
#pragma unroll
        for (int hh = 0; hh < 2; hh++) {
            sa[mt][hh] += __shfl_xor_sync(0xffffffffu, sa[mt][hh], 1);
            sa[mt][hh] += __shfl_xor_sync(0xffffffffu, sa[mt][hh], 2);
            sd[mt][hh] += __shfl_xor_sync(0xffffffffu, sd[mt][hh], 1);
            sd[mt][hh] += __shfl_xor_sync(0xffffffffu, sd[mt][hh], 2);
        }

#pragma unroll
    for (int mt = 0; mt < 2; mt++) {
        int r0 = m0 + wm * 32 + mt * 16 + g4;
#pragma unroll
        for (int nt = 0; nt < 8; nt++) {
            int nc = wn * 64 + nt * 8 + tg * 2;
            if (r0 < NN)
                *reinterpret_cast<unsigned*>(&out[(size_t)r0 * 256 + nc]) =
                    pack_bf16x2(c[mt][nt][0], c[mt][nt][1]);
            if (r0 + 8 < NN)
                *reinterpret_cast<unsigned*>(&out[(size_t)(r0 + 8) * 256 + nc]) =
                    pack_bf16x2(c[mt][nt][2], c[mt][nt][3]);
        }
        if (tg == 0) {
            if (r0 < NN)     { g_as[r0 * 4 + head]       = sa[mt][0]; g_ad[r0 * 4 + head]       = sd[mt][0]; }
            if (r0 + 8 < NN) { g_as[(r0 + 8) * 4 + head] = sa[mt][1]; g_ad[(r0 + 8) * 4 + head] = sd[mt][1]; }
        }
    }
#undef FILLB
}

// ---------------- edge aggregation: SINGLE PASS, MLP-4 ----------------
__device__ __forceinline__ float leaky(float x) { return x > 0.f ? x : 0.2f * x; }

template <int MODE>
__global__ void aggregate_kernel(const __nv_bfloat16* __restrict__ h,
                                 const float* __restrict__ bias,
                                 const float* __restrict__ lng,
                                 const float* __restrict__ lnb,
                                 const int* __restrict__ batch,
                                 __nv_bfloat16* __restrict__ bas_out)
{
    __shared__ float sp[256];
    __shared__ int bg_s;
    int wid = threadIdx.x >> 5;
    int lane = threadIdx.x & 31;
    int i = blockIdx.x * 8 + wid;   // grid covers exactly NN warps

    int my_g = 0;
    if (MODE == 1) {
        my_g = batch[i];
        if (threadIdx.x == 0) bg_s = my_g;
        sp[threadIdx.x] = 0.f;
        __syncthreads();
    }

    int p0 = g_indptr[i];
    int p1 = g_indptr[i + 1];
    int head = lane >> 3;
    float adh = g_ad[i * 4 + head];

    float acc[8];
#pragma unroll
    for (int k = 0; k < 8; k++) acc[k] = 0.f;
    float den = 0.f;

#define ACC4(U, W) \
    f = bf2_to_f2(U.x); acc[0] += W * f.x; acc[1] += W * f.y; \
    f = bf2_to_f2(U.y); acc[2] += W * f.x; acc[3] += W * f.y; \
    f = bf2_to_f2(U.z); acc[4] += W * f.x; acc[5] += W * f.y; \
    f = bf2_to_f2(U.w); acc[6] += W * f.x; acc[7] += W * f.y;

    int j = p0;
    for (; j + 3 < p1; j += 4) {
        int s0 = g_ssrc[j], s1 = g_ssrc[j + 1], s2 = g_ssrc[j + 2], s3 = g_ssrc[j + 3];
        uint4 u0 = *reinterpret_cast<const uint4*>(h + (size_t)s0 * 256 + lane * 8);
        uint4 u1 = *reinterpret_cast<const uint4*>(h + (size_t)s1 * 256 + lane * 8);
        uint4 u2 = *reinterpret_cast<const uint4*>(h + (size_t)s2 * 256 + lane * 8);
        uint4 u3 = *reinterpret_cast<const uint4*>(h + (size_t)s3 * 256 + lane * 8);
        float a0 = g_as[s0 * 4 + head], a1 = g_as[s1 * 4 + head];
        float a2 = g_as[s2 * 4 + head], a3 = g_as[s3 * 4 + head];
        float w0 = __expf(leaky(a0 + adh));
        float w1 = __expf(leaky(a1 + adh));
        float w2 = __expf(leaky(a2 + adh));
        float w3 = __expf(leaky(a3 + adh));
        den += (w0 + w1) + (w2 + w3);
        float2 f;
        ACC4(u0, w0) ACC4(u1, w1) ACC4(u2, w2) ACC4(u3, w3)
    }
    for (; j < p1; j++) {
        int s = g_ssrc[j];
        uint4 u = *reinterpret_cast<const uint4*>(h + (size_t)s * 256 + lane * 8);
        float w = __expf(leaky(g_as[s * 4 + head] + adh));
        den += w;
        float2 f;
        ACC4(u, w)
    }
#undef ACC4

    float inv = 1.f / den;
    int cb = lane * 8;
    float r[8];
#pragma unroll
    for (int k = 0; k < 8; k++) {
        float v = acc[k] * inv + bias[cb + k];
        r[k] = v / (1.f + __expf(-v));   // silu
    }

    if (MODE == 0) {
        float s = 0.f, ss = 0.f;
#pragma unroll
        for (int k = 0; k < 8; k++) { s += r[k]; ss += r[k] * r[k]; }
#pragma unroll
        for (int off = 16; off > 0; off >>= 1) {
            s  += __shfl_xor_sync(0xffffffffu, s, off);
            ss += __shfl_xor_sync(0xffffffffu, ss, off);
        }
        float mean = s / 256.f;
        float rstd = rsqrtf(ss / 256.f - mean * mean + 1e-5f);
        float4 g0 = *reinterpret_cast<const float4*>(&lng[cb]);
        float4 g1 = *reinterpret_cast<const float4*>(&lng[cb + 4]);
        float4 b0 = *reinterpret_cast<const float4*>(&lnb[cb]);
        float4 b1 = *reinterpret_cast<const float4*>(&lnb[cb + 4]);
        float o[8];
        o[0] = (r[0]-mean)*rstd*g0.x + b0.x; o[1] = (r[1]-mean)*rstd*g0.y + b0.y;
        o[2] = (r[2]-mean)*rstd*g0.z + b0.z; o[3] = (r[3]-mean)*rstd*g0.w + b0.w;
        o[4] = (r[4]-mean)*rstd*g1.x + b1.x; o[5] = (r[5]-mean)*rstd*g1.y + b1.y;
        o[6] = (r[6]-mean)*rstd*g1.z + b1.z; o[7] = (r[7]-mean)*rstd*g1.w + b1.w;
        unsigned pk[16];
#pragma unroll
        for (int k = 0; k < 8; k++) {
            float bv[4];
            rbf4(o[k], bv);
            pk[k * 2]     = pack_bf16x2(bv[0], bv[1]);
            pk[k * 2 + 1] = pack_bf16x2(bv[2], bv[3]);
        }
        uint4* bp = reinterpret_cast<uint4*>(&bas_out[(size_t)i * 1024 + cb * 4]);
        bp[0] = make_uint4(pk[0],  pk[1],  pk[2],  pk[3]);
        bp[1] = make_uint4(pk[4],  pk[5],  pk[6],  pk[7]);
        bp[2] = make_uint4(pk[8],  pk[9],  pk[10], pk[11]);
        bp[3] = make_uint4(pk[12], pk[13], pk[14], pk[15]);
    } else {
        int bg = bg_s;
        if (my_g == bg) {
#pragma unroll
            for (int k = 0; k < 8; k++) atomicAdd(&sp[cb + k], r[k]);
        } else {
#pragma unroll
            for (int k = 0; k < 8; k++) atomicAdd(&g_pooled[my_g * 256 + cb + k], r[k]);
        }
        __syncthreads();
        atomicAdd(&g_pooled[bg * 256 + threadIdx.x], sp[threadIdx.x]);
    }
}

// ---------------- readout ----------------
__global__ void readout_kernel(const float* __restrict__ lng, const float* __restrict__ lnb,
                               const float* __restrict__ Wr, float* __restrict__ out)
{
    __shared__ float bas[1024];
    __shared__ float red[16];
    __shared__ float logit[16];
    __shared__ float mean_s, rstd_s;
    int gidx = blockIdx.x, t = threadIdx.x;
    int lane = t & 31, w = t >> 5;

    float v = g_pooled[gidx * 256 + t];
    float s = v, ss = v * v;
#pragma unroll
    for (int off = 16; off > 0; off >>= 1) {
        s  += __shfl_xor_sync(0xffffffffu, s, off);
        ss += __shfl_xor_sync(0xffffffffu, ss, off);
    }
    if (lane == 0) { red[w] = s; red[8 + w] = ss; }
    __syncthreads();
    if (t == 0) {
        float S = 0.f, SS = 0.f;
        for (int k = 0; k < 8; k++) { S += red[k]; SS += red[8 + k]; }
        float mean = S / 256.f;
        float var  = SS / 256.f - mean * mean;
        mean_s = mean; rstd_s = rsqrtf(var + 1e-5f);
    }
    __syncthreads();
    float ln = (v - mean_s) * rstd_s * lng[t] + lnb[t];
    {
        float bv[4];
        rbf4(ln, bv);
        bas[t * 4 + 0] = bv[0];
        bas[t * 4 + 1] = bv[1];
        bas[t * 4 + 2] = bv[2];
        bas[t * 4 + 3] = bv[3];
    }
    __syncthreads();

    float p0 = 0.f, p1 = 0.f;
    const float* w0 = Wr + (size_t)(2 * w) * 1024;
    const float* w1 = w0 + 1024;
    for (int k = lane; k < 1024; k += 32) {
        float bv = bas[k];
        p0 += bv * w0[k];
        p1 += bv * w1[k];
    }
#pragma unroll
    for (int off = 16; off > 0; off >>= 1) {
        p0 += __shfl_xor_sync(0xffffffffu, p0, off);
        p1 += __shfl_xor_sync(0xffffffffu, p1, off);
    }
    if (lane == 0) { logit[2 * w] = p0; logit[2 * w + 1] = p1; }
    __syncthreads();

    if (t < 32) {
        float l = (lane < 16) ? logit[lane] : -1e30f;
        float m = l;
#pragma unroll
        for (int off = 16; off > 0; off >>= 1)
            m = fmaxf(m, __shfl_xor_sync(0xffffffffu, m, off));
        float ex = (lane < 16) ? __expf(l - m) : 0.f;
        float sum = ex;
#pragma unroll
        for (int off = 16; off > 0; off >>= 1)
            sum += __shfl_xor_sync(0xffffffffu, sum, off);
        if (lane < 16) out[gidx * 16 + lane] = l - m - logf(sum);
    }
}

// ---------------- launch ----------------
extern "C" void kernel_launch(void* const* d_in, const int* in_sizes, int n_in,
                              void* d_out, int out_size)
{
    const float* x     = (const float*)d_in[0];
    const int*   ei    = (const int*)  d_in[1];
    const int*   batch = (const int*)  d_in[2];
    const float* lng0  = (const float*)d_in[3];
    const float* lnb0  = (const float*)d_in[4];
    const float* W0    = (const float*)d_in[5];
    const float* as0   = (const float*)d_in[6];
    const float* ad0   = (const float*)d_in[7];
    const float* b0    = (const float*)d_in[8];
    const float* lng1  = (const float*)d_in[9];
    const float* lnb1  = (const float*)d_in[10];
    const float* W1    = (const float*)d_in[11];
    const float* as1   = (const float*)d_in[12];
    const float* ad1   = (const float*)d_in[13];
    const float* b1    = (const float*)d_in[14];
    const float* lngr  = (const float*)d_in[15];
    const float* lnbr  = (const float*)d_in[16];
    const float* Wr    = (const float*)d_in[17];
    float* out = (float*)d_out;

    __nv_bfloat16 *h_p, *bas_p, *wh0_p, *wh1_p;
    cudaGetSymbolAddress((void**)&h_p,    g_h);
    cudaGetSymbolAddress((void**)&bas_p,  g_bas);
    cudaGetSymbolAddress((void**)&wh0_p,  g_Wh0);
    cudaGetSymbolAddress((void**)&wh1_p,  g_Wh1);

    static cudaStream_t s2 = nullptr, s3 = nullptr;
    static cudaEvent_t ev_fork = nullptr, ev_side = nullptr, ev_w0 = nullptr, ev_w1 = nullptr;
    if (!s2) {
        cudaStreamCreateWithFlags(&s2, cudaStreamNonBlocking);
        cudaStreamCreateWithFlags(&s3, cudaStreamNonBlocking);
        cudaEventCreateWithFlags(&ev_fork, cudaEventDisableTiming);
        cudaEventCreateWithFlags(&ev_side, cudaEventDisableTiming);
        cudaEventCreateWithFlags(&ev_w0, cudaEventDisableTiming);
        cudaEventCreateWithFlags(&ev_w1, cudaEventDisableTiming);
    }

    cudaFuncSetAttribute((const void*)kan_bf16<128, 0>,
                         cudaFuncAttributeMaxDynamicSharedMemorySize, SM_BYTES_BF);
    cudaFuncSetAttribute((const void*)kan_bf16<256, 1>,
                         cudaFuncAttributeMaxDynamicSharedMemorySize, SM_BYTES_BF);

    const int TPB = 256;
    const int scan_blocks = (NN + 1023) / 1024;
    int warp_blocks = (NN * 32 + TPB - 1) / TPB;   // 6250 (exact)
    int gemm_blocks = (NN + 63) / 64;              // 782

    // ---- fork side streams ----
    cudaEventRecord(ev_fork, 0);
    cudaStreamWaitEvent(s2, ev_fork, 0);
    cudaStreamWaitEvent(s3, ev_fork, 0);

    // s2: CSR build only (shortened: clear & init_cursor fused away)
    hist_kernel<<<(NE + TPB - 1) / TPB, TPB, 0, s2>>>(ei);
    scan_part1<<<scan_blocks, 256, 0, s2>>>();
    scan_part2<<<1, 64, 0, s2>>>(scan_blocks);
    scan_part3<<<scan_blocks, 1024, 0, s2>>>();
    scatter_kernel<<<(NE + TPB - 1) / TPB, TPB, 0, s2>>>(ei);
    cudaEventRecord(ev_side, s2);

    // s3: weight converts (W0 gates kan128; W1 gates kan256)
    cvt_w_kernel<<<(256 * 512 / 4 + TPB - 1) / TPB, TPB, 0, s3>>>(W0, wh0_p, 256 * 512 / 4);
    cudaEventRecord(ev_w0, s3);
    cvt_w_kernel<<<(256 * 1024 / 4 + TPB - 1) / TPB, TPB, 0, s3>>>(W1, wh1_p, 256 * 1024 / 4);
    cudaEventRecord(ev_w1, s3);

    // ---- main: layer-0 GEMM with fused input LayerNorm ----
    cudaStreamWaitEvent(0, ev_w0, 0);
    kan_bf16<128, 0><<<gemm_blocks, TPB, SM_BYTES_BF>>>(x, nullptr, lng0, lnb0, wh0_p, as0, ad0, h_p);

    // ---- join: aggregate needs CSR (side) + h/alphas (main) ----
    cudaStreamWaitEvent(0, ev_side, 0);
    aggregate_kernel<0><<<warp_blocks, TPB>>>(h_p, b0, lng1, lnb1, batch, bas_p);
    // layer 1 (A tile streamed from precomputed basis)
    cudaStreamWaitEvent(0, ev_w1, 0);
    kan_bf16<256, 1><<<gemm_blocks, TPB, SM_BYTES_BF>>>(nullptr, bas_p, nullptr, nullptr, wh1_p, as1, ad1, h_p);
    aggregate_kernel<1><<<warp_blocks, TPB>>>(h_p, b1, nullptr, nullptr, batch, nullptr);
    // readout
    readout_kernel<<<NG, 256>>>(lngr, lnbr, Wr, out);
}